// round 10
// baseline (speedup 1.0000x reference)
#include <cuda_runtime.h>
#include <cuda_bf16.h>
#include <cuda_fp16.h>
#include <cstdint>

#define BATCH 2
#define SEQN 4096
#define CDIM 256
#define NH 8
#define DH 32
#define TWOC 512
#define SCALE 25.0f
// exp(25*d - 12) = exp2(d*25*log2e - 12*log2e)
#define EXP_A 36.06737602f
#define EXP_B 17.31234049f

#define ROWS 16            // q rows per CTA
#define CHUNK 256          // keys per chunk
#define NCHUNK (SEQN / CHUNK)

// -------- device scratch (no cudaMalloc allowed) --------
__device__ float g_qkv[BATCH * SEQN * TWOC];                       // 16 MB
__device__ __nv_bfloat16 g_qh[BATCH * NH * SEQN * DH];             // 4 MB
__device__ __nv_bfloat16 g_ql[BATCH * NH * SEQN * DH];             // 4 MB
__device__ __nv_bfloat16 g_kh[BATCH * NH * SEQN * DH];             // 4 MB
__device__ __nv_bfloat16 g_kl[BATCH * NH * SEQN * DH];             // 4 MB
__device__ __half g_e[(size_t)BATCH * NH * SEQN * SEQN];           // 536 MB fp16 exp scratch

// ---------------------------------------------------------------------------
// Dummy kernel: shifts ncu's fixed capture slot (-s 5 -c 1) onto the attn
// kernel so the profile finally shows the hot kernel instead of qkv.
// ---------------------------------------------------------------------------
__global__ void dummy_kernel() {}

// ---------------------------------------------------------------------------
// Kernel 1: qkv = x @ W   (M=8192, N=512, K=256)
// ---------------------------------------------------------------------------
__global__ __launch_bounds__(256) void qkv_gemm_kernel(
    const float* __restrict__ x, const float* __restrict__ w)
{
    __shared__ float As[64][17];
    __shared__ float Bs[16][65];

    const int tid = threadIdx.x;
    const int tx = tid & 15;
    const int ty = tid >> 4;
    const int rowBase = blockIdx.y * 64;
    const int colBase = blockIdx.x * 64;

    float acc[4][4];
#pragma unroll
    for (int i = 0; i < 4; i++)
#pragma unroll
        for (int j = 0; j < 4; j++) acc[i][j] = 0.f;

    for (int k0 = 0; k0 < CDIM; k0 += 16) {
        {
            const int r = tid >> 2;
            const int kk = (tid & 3) * 4;
            float4 a = *reinterpret_cast<const float4*>(
                x + (size_t)(rowBase + r) * CDIM + k0 + kk);
            As[r][kk + 0] = a.x; As[r][kk + 1] = a.y;
            As[r][kk + 2] = a.z; As[r][kk + 3] = a.w;
        }
        {
            const int r = tid >> 4;
            const int c = (tid & 15) * 4;
            float4 b = *reinterpret_cast<const float4*>(
                w + (size_t)(k0 + r) * TWOC + colBase + c);
            Bs[r][c + 0] = b.x; Bs[r][c + 1] = b.y;
            Bs[r][c + 2] = b.z; Bs[r][c + 3] = b.w;
        }
        __syncthreads();

#pragma unroll
        for (int kk = 0; kk < 16; kk++) {
            float ar[4], br[4];
#pragma unroll
            for (int i = 0; i < 4; i++) ar[i] = As[ty * 4 + i][kk];
#pragma unroll
            for (int j = 0; j < 4; j++) br[j] = Bs[kk][tx * 4 + j];
#pragma unroll
            for (int i = 0; i < 4; i++)
#pragma unroll
                for (int j = 0; j < 4; j++) acc[i][j] += ar[i] * br[j];
        }
        __syncthreads();
    }

#pragma unroll
    for (int i = 0; i < 4; i++) {
        float* orow = g_qkv + (size_t)(rowBase + ty * 4 + i) * TWOC + colBase + tx * 4;
#pragma unroll
        for (int j = 0; j < 4; j++) orow[j] = acc[i][j];
    }
}

// ---------------------------------------------------------------------------
// Kernel 1b: normalize + bf16 hi/lo split, layout [b*H+h][n][d]
// ---------------------------------------------------------------------------
__global__ __launch_bounds__(256) void prep_kernel()
{
    const int lane = threadIdx.x & 31;
    const int wid = blockIdx.x * 8 + (threadIdx.x >> 5);
    const int row = wid >> 4;
    const int rem = wid & 15;
    const int which = rem >> 3;
    const int h = rem & 7;

    float v = g_qkv[(size_t)row * TWOC + which * CDIM + h * DH + lane];
    float ss = v * v;
#pragma unroll
    for (int o = 16; o > 0; o >>= 1) ss += __shfl_xor_sync(0xffffffffu, ss, o);
    float nv = v / (sqrtf(ss) + 1e-8f);

    __nv_bfloat16 hi = __float2bfloat16_rn(nv);
    __nv_bfloat16 lo = __float2bfloat16_rn(nv - __bfloat162float(hi));

    const int b = row >> 12;
    const int n = row & 4095;
    const size_t dst = ((size_t)(b * NH + h) * SEQN + n) * DH + lane;
    if (which == 0) { g_qh[dst] = hi; g_ql[dst] = lo; }
    else            { g_kh[dst] = hi; g_kl[dst] = lo; }
}

// ---------------------------------------------------------------------------
// Kernel 2: single-pass scores + exp (fp16 -> gmem scratch) + rowsums,
// then per-CTA L2-hot readback, rescale, coalesced fp32 store.
// MMA schedule: term-outer / n-tile-inner -> 4 independent accumulator
// chains, consecutive HMMAs never RAW-dependent.
// ---------------------------------------------------------------------------

// smem byte offsets
#define OFF_KH   0u          // 2 bufs x 256 rows x 80 B
#define OFF_KL   40960u
#define OFF_QH   81920u      // 16 rows x 80 B
#define OFF_QL   83200u
#define OFF_RS   84480u      // 16 floats
#define OFF_INV  84544u      // 16 floats
#define SMEM_BYTES 84608u
#define KBUF_STRIDE 20480u

__device__ __forceinline__ void cp_async16(uint32_t smem_dst, const void* gsrc) {
    asm volatile("cp.async.cg.shared.global [%0], [%1], 16;\n"
                 :: "r"(smem_dst), "l"(gsrc));
}
__device__ __forceinline__ void cp_commit() {
    asm volatile("cp.async.commit_group;\n");
}
template <int N>
__device__ __forceinline__ void cp_wait() {
    asm volatile("cp.async.wait_group %0;\n" :: "n"(N));
}

__device__ __forceinline__ void mma_bf16(float* d,
                                         const uint32_t* a,
                                         uint32_t b0, uint32_t b1) {
    asm volatile(
        "mma.sync.aligned.m16n8k16.row.col.f32.bf16.bf16.f32 "
        "{%0,%1,%2,%3}, {%4,%5,%6,%7}, {%8,%9}, {%0,%1,%2,%3};"
        : "+f"(d[0]), "+f"(d[1]), "+f"(d[2]), "+f"(d[3])
        : "r"(a[0]), "r"(a[1]), "r"(a[2]), "r"(a[3]), "r"(b0), "r"(b1));
}

__global__ __launch_bounds__(256, 2) void attn_softmax_kernel(float* __restrict__ out)
{
    extern __shared__ char smem[];
    const uint32_t sbase = (uint32_t)__cvta_generic_to_shared(smem);

    const int tid = threadIdx.x;
    const int w = tid >> 5;               // warp 0..7
    const int lane = tid & 31;
    const int g = lane >> 2;              // row group 0..7
    const int t = lane & 3;               // quad id

    const int bh = blockIdx.y;            // 0..15
    const int qBase = blockIdx.x * ROWS;

    const __nv_bfloat16* qh = g_qh + ((size_t)bh * SEQN + qBase) * DH;
    const __nv_bfloat16* ql = g_ql + ((size_t)bh * SEQN + qBase) * DH;
    const __nv_bfloat16* kh = g_kh + (size_t)bh * SEQN * DH;
    const __nv_bfloat16* kl = g_kl + (size_t)bh * SEQN * DH;
    __half* ebase = g_e + ((size_t)bh * SEQN + qBase) * SEQN;

    // ---- Q tile into padded smem (16 rows x 32 halves, 80 B stride) ----
    for (int i = tid; i < ROWS * DH; i += 256) {
        const int r = i >> 5, d = i & 31;
        *reinterpret_cast<__nv_bfloat16*>(smem + OFF_QH + r * 80 + d * 2) = qh[i];
        *reinterpret_cast<__nv_bfloat16*>(smem + OFF_QL + r * 80 + d * 2) = ql[i];
    }
    if (tid < ROWS) *reinterpret_cast<float*>(smem + OFF_RS + tid * 4) = 0.f;

    // ---- issue chunk 0 (kh + kl) ----
#pragma unroll
    for (int s = 0; s < 4; s++) {
        const int task = tid + 256 * s;
        const int r = task >> 2, seg = task & 3;
        cp_async16(sbase + OFF_KH + (uint32_t)(r * 80 + seg * 16),
                   (const char*)kh + r * 64 + seg * 16);
        cp_async16(sbase + OFF_KL + (uint32_t)(r * 80 + seg * 16),
                   (const char*)kl + r * 64 + seg * 16);
    }
    cp_commit();
    __syncthreads();

    // ---- A fragments (fixed for whole kernel) ----
    uint32_t aH[2][4], aL[2][4];
#pragma unroll
    for (int ks = 0; ks < 2; ks++) {
        const int c0 = ks * 16;
#pragma unroll
        for (int i = 0; i < 4; i++) {
            const int rr = (i & 1) ? g + 8 : g;
            const int cc = c0 + 2 * t + ((i >> 1) ? 8 : 0);
            aH[ks][i] = *reinterpret_cast<const uint32_t*>(smem + OFF_QH + rr * 80 + cc * 2);
            aL[ks][i] = *reinterpret_cast<const uint32_t*>(smem + OFF_QL + rr * 80 + cc * 2);
        }
    }

    float p_lo = 0.f, p_hi = 0.f;         // rowsum partials (rows g, g+8)

    for (int c = 0; c < NCHUNK; c++) {
        if (c + 1 < NCHUNK) {
            const uint32_t boff = ((c + 1) & 1) * KBUF_STRIDE;
            const char* khp = (const char*)kh + (size_t)(c + 1) * CHUNK * 64;
            const char* klp = (const char*)kl + (size_t)(c + 1) * CHUNK * 64;
#pragma unroll
            for (int s = 0; s < 4; s++) {
                const int task = tid + 256 * s;
                const int r = task >> 2, seg = task & 3;
                cp_async16(sbase + OFF_KH + boff + (uint32_t)(r * 80 + seg * 16),
                           khp + r * 64 + seg * 16);
                cp_async16(sbase + OFF_KL + boff + (uint32_t)(r * 80 + seg * 16),
                           klp + r * 64 + seg * 16);
            }
            cp_commit();
            cp_wait<1>();
        } else {
            cp_wait<0>();
        }
        __syncthreads();

        const uint32_t boff = (c & 1) * KBUF_STRIDE;
        const char* khS = smem + OFF_KH + boff;
        const char* klS = smem + OFF_KL + boff;

        // ---- load ALL B fragments for the 4 n-tiles ----
        uint32_t bH[4][2][2], bL[4][2][2];
#pragma unroll
        for (int nt = 0; nt < 4; nt++) {
            const int kb = w * 32 + nt * 8 + g;
#pragma unroll
            for (int ks = 0; ks < 2; ks++) {
                const int c0 = ks * 16;
                bH[nt][ks][0] = *reinterpret_cast<const uint32_t*>(khS + kb * 80 + (c0 + 2 * t) * 2);
                bH[nt][ks][1] = *reinterpret_cast<const uint32_t*>(khS + kb * 80 + (c0 + 2 * t + 8) * 2);
                bL[nt][ks][0] = *reinterpret_cast<const uint32_t*>(klS + kb * 80 + (c0 + 2 * t) * 2);
                bL[nt][ks][1] = *reinterpret_cast<const uint32_t*>(klS + kb * 80 + (c0 + 2 * t + 8) * 2);
            }
        }

        // ---- 4 independent accumulator chains, term-outer schedule ----
        float acc[4][4];
#pragma unroll
        for (int nt = 0; nt < 4; nt++)
#pragma unroll
            for (int i = 0; i < 4; i++) acc[nt][i] = 0.f;

#pragma unroll
        for (int ks = 0; ks < 2; ks++) {
#pragma unroll
            for (int nt = 0; nt < 4; nt++)
                mma_bf16(acc[nt], aH[ks], bH[nt][ks][0], bH[nt][ks][1]);
#pragma unroll
            for (int nt = 0; nt < 4; nt++)
                mma_bf16(acc[nt], aL[ks], bH[nt][ks][0], bH[nt][ks][1]);
#pragma unroll
            for (int nt = 0; nt < 4; nt++)
                mma_bf16(acc[nt], aH[ks], bL[nt][ks][0], bL[nt][ks][1]);
        }

        // ---- epilogue: exp2-folded, fp16 to gmem scratch, rowsums ----
#pragma unroll
        for (int nt = 0; nt < 4; nt++) {
            const int col = c * CHUNK + w * 32 + nt * 8 + 2 * t;   // even
            float e0 = exp2f(fmaf(acc[nt][0], EXP_A, -EXP_B));
            float e1 = exp2f(fmaf(acc[nt][1], EXP_A, -EXP_B));
            float e2 = exp2f(fmaf(acc[nt][2], EXP_A, -EXP_B));
            float e3 = exp2f(fmaf(acc[nt][3], EXP_A, -EXP_B));
            *reinterpret_cast<__half2*>(ebase + (size_t)g * SEQN + col) =
                __floats2half2_rn(e0, e1);
            *reinterpret_cast<__half2*>(ebase + (size_t)(g + 8) * SEQN + col) =
                __floats2half2_rn(e2, e3);
            p_lo += e0 + e1;
            p_hi += e2 + e3;
        }
        __syncthreads();   // protect buffer (c&1) before refill at c+1
    }

    // ---- rowsum reduce: quad shuffle + smem atomics ----
    p_lo += __shfl_xor_sync(0xffffffffu, p_lo, 1);
    p_lo += __shfl_xor_sync(0xffffffffu, p_lo, 2);
    p_hi += __shfl_xor_sync(0xffffffffu, p_hi, 1);
    p_hi += __shfl_xor_sync(0xffffffffu, p_hi, 2);
    if (t == 0) {
        atomicAdd(reinterpret_cast<float*>(smem + OFF_RS + g * 4), p_lo);
        atomicAdd(reinterpret_cast<float*>(smem + OFF_RS + (g + 8) * 4), p_hi);
    }
    __syncthreads();
    if (tid < ROWS) {
        float s = *reinterpret_cast<float*>(smem + OFF_RS + tid * 4);
        *reinterpret_cast<float*>(smem + OFF_INV + tid * 4) = 1.f / s;
    }
    __syncthreads();

    // ---- readback (L2-hot) + rescale + coalesced fp32 stores ----
    float* obase = out + ((size_t)bh * SEQN + qBase) * SEQN;
    for (int j = tid * 8; j < ROWS * SEQN; j += 2048) {
        const int row = j >> 12;
        const int col = j & 4095;
        uint4 v = *reinterpret_cast<const uint4*>(ebase + (size_t)row * SEQN + col);
        const float inv = *reinterpret_cast<float*>(smem + OFF_INV + row * 4);
        float2 f0 = __half22float2(*reinterpret_cast<__half2*>(&v.x));
        float2 f1 = __half22float2(*reinterpret_cast<__half2*>(&v.y));
        float2 f2 = __half22float2(*reinterpret_cast<__half2*>(&v.z));
        float2 f3 = __half22float2(*reinterpret_cast<__half2*>(&v.w));
        float4 o0, o1;
        o0.x = f0.x * inv; o0.y = f0.y * inv; o0.z = f1.x * inv; o0.w = f1.y * inv;
        o1.x = f2.x * inv; o1.y = f2.y * inv; o1.z = f3.x * inv; o1.w = f3.y * inv;
        float* op = obase + (size_t)row * SEQN + col;
        *reinterpret_cast<float4*>(op) = o0;
        *reinterpret_cast<float4*>(op + 4) = o1;
    }
}

// ---------------------------------------------------------------------------
extern "C" void kernel_launch(void* const* d_in, const int* in_sizes, int n_in,
                              void* d_out, int out_size)
{
    const float* x = (const float*)d_in[0];    // [2,4096,256]
    const float* wmat = (const float*)d_in[1]; // [256,512]
    float* out = (float*)d_out;                // [2,8,4096,4096]

    dummy_kernel<<<1, 32>>>();                 // ncu capture-slot shim

    dim3 g1(TWOC / 64, (BATCH * SEQN) / 64);   // (8, 128)
    qkv_gemm_kernel<<<g1, 256>>>(x, wmat);

    prep_kernel<<<(BATCH * SEQN * 16) / 8, 256>>>();

    cudaFuncSetAttribute(attn_softmax_kernel,
                         cudaFuncAttributeMaxDynamicSharedMemorySize, SMEM_BYTES);
    dim3 g2(SEQN / ROWS, BATCH * NH);          // (256, 16)
    attn_softmax_kernel<<<g2, 256, SMEM_BYTES>>>(out);
}

// round 11
// speedup vs baseline: 1.5649x; 1.5649x over previous
#include <cuda_runtime.h>
#include <cuda_bf16.h>
#include <cuda_fp16.h>
#include <cstdint>

#define BATCH 2
#define SEQN 4096
#define CDIM 256
#define NH 8
#define DH 32
#define TWOC 512
#define SCALE 25.0f
// exp(25*d - 12) = exp2(d*25*log2e - 12*log2e)
#define EXP_A 36.06737602f
#define EXP_B 17.31234049f

#define ROWS 16            // q rows per CTA
#define CHUNK 128          // keys per chunk (halved -> 4 CTAs/SM)
#define NCHUNK (SEQN / CHUNK)

// -------- device scratch (no cudaMalloc allowed) --------
__device__ float g_qkv[BATCH * SEQN * TWOC];                       // 16 MB
__device__ __nv_bfloat16 g_qh[BATCH * NH * SEQN * DH];             // 4 MB
__device__ __nv_bfloat16 g_ql[BATCH * NH * SEQN * DH];             // 4 MB
__device__ __nv_bfloat16 g_kh[BATCH * NH * SEQN * DH];             // 4 MB
__device__ __nv_bfloat16 g_kl[BATCH * NH * SEQN * DH];             // 4 MB
__device__ __half g_e[(size_t)BATCH * NH * SEQN * SEQN];           // 536 MB fp16 exp scratch

// ---------------------------------------------------------------------------
// Dummy kernel: keeps ncu's fixed capture slot on the attn kernel.
// ---------------------------------------------------------------------------
__global__ void dummy_kernel() {}

// ---------------------------------------------------------------------------
// Kernel 1: qkv = x @ W   (M=8192, N=512, K=256)
// ---------------------------------------------------------------------------
__global__ __launch_bounds__(256) void qkv_gemm_kernel(
    const float* __restrict__ x, const float* __restrict__ w)
{
    __shared__ float As[64][17];
    __shared__ float Bs[16][65];

    const int tid = threadIdx.x;
    const int tx = tid & 15;
    const int ty = tid >> 4;
    const int rowBase = blockIdx.y * 64;
    const int colBase = blockIdx.x * 64;

    float acc[4][4];
#pragma unroll
    for (int i = 0; i < 4; i++)
#pragma unroll
        for (int j = 0; j < 4; j++) acc[i][j] = 0.f;

    for (int k0 = 0; k0 < CDIM; k0 += 16) {
        {
            const int r = tid >> 2;
            const int kk = (tid & 3) * 4;
            float4 a = *reinterpret_cast<const float4*>(
                x + (size_t)(rowBase + r) * CDIM + k0 + kk);
            As[r][kk + 0] = a.x; As[r][kk + 1] = a.y;
            As[r][kk + 2] = a.z; As[r][kk + 3] = a.w;
        }
        {
            const int r = tid >> 4;
            const int c = (tid & 15) * 4;
            float4 b = *reinterpret_cast<const float4*>(
                w + (size_t)(k0 + r) * TWOC + colBase + c);
            Bs[r][c + 0] = b.x; Bs[r][c + 1] = b.y;
            Bs[r][c + 2] = b.z; Bs[r][c + 3] = b.w;
        }
        __syncthreads();

#pragma unroll
        for (int kk = 0; kk < 16; kk++) {
            float ar[4], br[4];
#pragma unroll
            for (int i = 0; i < 4; i++) ar[i] = As[ty * 4 + i][kk];
#pragma unroll
            for (int j = 0; j < 4; j++) br[j] = Bs[kk][tx * 4 + j];
#pragma unroll
            for (int i = 0; i < 4; i++)
#pragma unroll
                for (int j = 0; j < 4; j++) acc[i][j] += ar[i] * br[j];
        }
        __syncthreads();
    }

#pragma unroll
    for (int i = 0; i < 4; i++) {
        float* orow = g_qkv + (size_t)(rowBase + ty * 4 + i) * TWOC + colBase + tx * 4;
#pragma unroll
        for (int j = 0; j < 4; j++) orow[j] = acc[i][j];
    }
}

// ---------------------------------------------------------------------------
// Kernel 1b: normalize + bf16 hi/lo split, layout [b*H+h][n][d]
// ---------------------------------------------------------------------------
__global__ __launch_bounds__(256) void prep_kernel()
{
    const int lane = threadIdx.x & 31;
    const int wid = blockIdx.x * 8 + (threadIdx.x >> 5);
    const int row = wid >> 4;
    const int rem = wid & 15;
    const int which = rem >> 3;
    const int h = rem & 7;

    float v = g_qkv[(size_t)row * TWOC + which * CDIM + h * DH + lane];
    float ss = v * v;
#pragma unroll
    for (int o = 16; o > 0; o >>= 1) ss += __shfl_xor_sync(0xffffffffu, ss, o);
    float nv = v / (sqrtf(ss) + 1e-8f);

    __nv_bfloat16 hi = __float2bfloat16_rn(nv);
    __nv_bfloat16 lo = __float2bfloat16_rn(nv - __bfloat162float(hi));

    const int b = row >> 12;
    const int n = row & 4095;
    const size_t dst = ((size_t)(b * NH + h) * SEQN + n) * DH + lane;
    if (which == 0) { g_qh[dst] = hi; g_ql[dst] = lo; }
    else            { g_kh[dst] = hi; g_kl[dst] = lo; }
}

// ---------------------------------------------------------------------------
// Kernel 2: single-pass scores + exp (fp16 -> gmem scratch) + rowsums,
// then per-CTA L2-hot readback, rescale, coalesced fp32 store.
// CHUNK=128, 43.6 KB smem -> 4 CTAs/SM (32 warps). R8 per-nt MMA schedule.
// ---------------------------------------------------------------------------

// smem byte offsets
#define OFF_KH   0u          // 2 bufs x 128 rows x 80 B
#define OFF_KL   20480u
#define OFF_QH   40960u      // 16 rows x 80 B
#define OFF_QL   42240u
#define OFF_RS   43520u      // 16 floats
#define OFF_INV  43584u      // 16 floats
#define SMEM_BYTES 43648u
#define KBUF_STRIDE 10240u

__device__ __forceinline__ void cp_async16(uint32_t smem_dst, const void* gsrc) {
    asm volatile("cp.async.cg.shared.global [%0], [%1], 16;\n"
                 :: "r"(smem_dst), "l"(gsrc));
}
__device__ __forceinline__ void cp_commit() {
    asm volatile("cp.async.commit_group;\n");
}
template <int N>
__device__ __forceinline__ void cp_wait() {
    asm volatile("cp.async.wait_group %0;\n" :: "n"(N));
}

__device__ __forceinline__ void mma_bf16(float& d0, float& d1, float& d2, float& d3,
                                         uint32_t a0, uint32_t a1, uint32_t a2, uint32_t a3,
                                         uint32_t b0, uint32_t b1) {
    asm volatile(
        "mma.sync.aligned.m16n8k16.row.col.f32.bf16.bf16.f32 "
        "{%0,%1,%2,%3}, {%4,%5,%6,%7}, {%8,%9}, {%0,%1,%2,%3};"
        : "+f"(d0), "+f"(d1), "+f"(d2), "+f"(d3)
        : "r"(a0), "r"(a1), "r"(a2), "r"(a3), "r"(b0), "r"(b1));
}

__global__ __launch_bounds__(256, 4) void attn_softmax_kernel(float* __restrict__ out)
{
    extern __shared__ char smem[];
    const uint32_t sbase = (uint32_t)__cvta_generic_to_shared(smem);

    const int tid = threadIdx.x;
    const int w = tid >> 5;               // warp 0..7
    const int lane = tid & 31;
    const int g = lane >> 2;              // row group 0..7
    const int t = lane & 3;               // quad id

    const int bh = blockIdx.y;            // 0..15
    const int qBase = blockIdx.x * ROWS;

    const __nv_bfloat16* qh = g_qh + ((size_t)bh * SEQN + qBase) * DH;
    const __nv_bfloat16* ql = g_ql + ((size_t)bh * SEQN + qBase) * DH;
    const __nv_bfloat16* kh = g_kh + (size_t)bh * SEQN * DH;
    const __nv_bfloat16* kl = g_kl + (size_t)bh * SEQN * DH;
    __half* ebase = g_e + ((size_t)bh * SEQN + qBase) * SEQN;

    // ---- Q tile into padded smem (16 rows x 32 halves, 80 B stride) ----
    for (int i = tid; i < ROWS * DH; i += 256) {
        const int r = i >> 5, d = i & 31;
        *reinterpret_cast<__nv_bfloat16*>(smem + OFF_QH + r * 80 + d * 2) = qh[i];
        *reinterpret_cast<__nv_bfloat16*>(smem + OFF_QL + r * 80 + d * 2) = ql[i];
    }
    if (tid < ROWS) *reinterpret_cast<float*>(smem + OFF_RS + tid * 4) = 0.f;

    // ---- issue chunk 0 (kh + kl): 128 rows x 4 segs = 512 tasks / plane ----
#pragma unroll
    for (int s = 0; s < 2; s++) {
        const int task = tid + 256 * s;
        const int r = task >> 2, seg = task & 3;
        cp_async16(sbase + OFF_KH + (uint32_t)(r * 80 + seg * 16),
                   (const char*)kh + r * 64 + seg * 16);
        cp_async16(sbase + OFF_KL + (uint32_t)(r * 80 + seg * 16),
                   (const char*)kl + r * 64 + seg * 16);
    }
    cp_commit();
    __syncthreads();

    // ---- A fragments (fixed for whole kernel) ----
    uint32_t aH[2][4], aL[2][4];
#pragma unroll
    for (int ks = 0; ks < 2; ks++) {
        const int c0 = ks * 16;
#pragma unroll
        for (int i = 0; i < 4; i++) {
            const int rr = (i & 1) ? g + 8 : g;
            const int cc = c0 + 2 * t + ((i >> 1) ? 8 : 0);
            aH[ks][i] = *reinterpret_cast<const uint32_t*>(smem + OFF_QH + rr * 80 + cc * 2);
            aL[ks][i] = *reinterpret_cast<const uint32_t*>(smem + OFF_QL + rr * 80 + cc * 2);
        }
    }

    float p_lo = 0.f, p_hi = 0.f;         // rowsum partials (rows g, g+8)

    for (int c = 0; c < NCHUNK; c++) {
        if (c + 1 < NCHUNK) {
            const uint32_t boff = ((c + 1) & 1) * KBUF_STRIDE;
            const char* khp = (const char*)kh + (size_t)(c + 1) * CHUNK * 64;
            const char* klp = (const char*)kl + (size_t)(c + 1) * CHUNK * 64;
#pragma unroll
            for (int s = 0; s < 2; s++) {
                const int task = tid + 256 * s;
                const int r = task >> 2, seg = task & 3;
                cp_async16(sbase + OFF_KH + boff + (uint32_t)(r * 80 + seg * 16),
                           khp + r * 64 + seg * 16);
                cp_async16(sbase + OFF_KL + boff + (uint32_t)(r * 80 + seg * 16),
                           klp + r * 64 + seg * 16);
            }
            cp_commit();
            cp_wait<1>();
        } else {
            cp_wait<0>();
        }
        __syncthreads();

        const uint32_t boff = (c & 1) * KBUF_STRIDE;
        const char* khS = smem + OFF_KH + boff;
        const char* klS = smem + OFF_KL + boff;

#pragma unroll
        for (int nt = 0; nt < 2; nt++) {
            const int kb = w * 16 + nt * 8 + g;   // key row within chunk
            uint32_t bH[2][2], bL[2][2];
#pragma unroll
            for (int ks = 0; ks < 2; ks++) {
                const int c0 = ks * 16;
                bH[ks][0] = *reinterpret_cast<const uint32_t*>(khS + kb * 80 + (c0 + 2 * t) * 2);
                bH[ks][1] = *reinterpret_cast<const uint32_t*>(khS + kb * 80 + (c0 + 2 * t + 8) * 2);
                bL[ks][0] = *reinterpret_cast<const uint32_t*>(klS + kb * 80 + (c0 + 2 * t) * 2);
                bL[ks][1] = *reinterpret_cast<const uint32_t*>(klS + kb * 80 + (c0 + 2 * t + 8) * 2);
            }

            float d0 = 0.f, d1 = 0.f, d2 = 0.f, d3 = 0.f;
#pragma unroll
            for (int ks = 0; ks < 2; ks++) {
                mma_bf16(d0, d1, d2, d3, aH[ks][0], aH[ks][1], aH[ks][2], aH[ks][3],
                         bH[ks][0], bH[ks][1]);
                mma_bf16(d0, d1, d2, d3, aL[ks][0], aL[ks][1], aL[ks][2], aL[ks][3],
                         bH[ks][0], bH[ks][1]);
                mma_bf16(d0, d1, d2, d3, aH[ks][0], aH[ks][1], aH[ks][2], aH[ks][3],
                         bL[ks][0], bL[ks][1]);
            }

            // epilogue: exp2-folded, fp16 to gmem scratch, rowsums
            const int col = c * CHUNK + w * 16 + nt * 8 + 2 * t;   // even
            float e0 = exp2f(fmaf(d0, EXP_A, -EXP_B));
            float e1 = exp2f(fmaf(d1, EXP_A, -EXP_B));
            float e2 = exp2f(fmaf(d2, EXP_A, -EXP_B));
            float e3 = exp2f(fmaf(d3, EXP_A, -EXP_B));
            *reinterpret_cast<__half2*>(ebase + (size_t)g * SEQN + col) =
                __floats2half2_rn(e0, e1);
            *reinterpret_cast<__half2*>(ebase + (size_t)(g + 8) * SEQN + col) =
                __floats2half2_rn(e2, e3);
            p_lo += e0 + e1;
            p_hi += e2 + e3;
        }
        __syncthreads();   // protect buffer (c&1) before refill at c+1
    }

    // ---- rowsum reduce: quad shuffle + smem atomics ----
    p_lo += __shfl_xor_sync(0xffffffffu, p_lo, 1);
    p_lo += __shfl_xor_sync(0xffffffffu, p_lo, 2);
    p_hi += __shfl_xor_sync(0xffffffffu, p_hi, 1);
    p_hi += __shfl_xor_sync(0xffffffffu, p_hi, 2);
    if (t == 0) {
        atomicAdd(reinterpret_cast<float*>(smem + OFF_RS + g * 4), p_lo);
        atomicAdd(reinterpret_cast<float*>(smem + OFF_RS + (g + 8) * 4), p_hi);
    }
    __syncthreads();
    if (tid < ROWS) {
        float s = *reinterpret_cast<float*>(smem + OFF_RS + tid * 4);
        *reinterpret_cast<float*>(smem + OFF_INV + tid * 4) = 1.f / s;
    }
    __syncthreads();

    // ---- readback (L2-hot) + rescale + coalesced fp32 stores ----
    float* obase = out + ((size_t)bh * SEQN + qBase) * SEQN;
    for (int j = tid * 8; j < ROWS * SEQN; j += 2048) {
        const int row = j >> 12;
        const int col = j & 4095;
        uint4 v = *reinterpret_cast<const uint4*>(ebase + (size_t)row * SEQN + col);
        const float inv = *reinterpret_cast<float*>(smem + OFF_INV + row * 4);
        float2 f0 = __half22float2(*reinterpret_cast<__half2*>(&v.x));
        float2 f1 = __half22float2(*reinterpret_cast<__half2*>(&v.y));
        float2 f2 = __half22float2(*reinterpret_cast<__half2*>(&v.z));
        float2 f3 = __half22float2(*reinterpret_cast<__half2*>(&v.w));
        float4 o0, o1;
        o0.x = f0.x * inv; o0.y = f0.y * inv; o0.z = f1.x * inv; o0.w = f1.y * inv;
        o1.x = f2.x * inv; o1.y = f2.y * inv; o1.z = f3.x * inv; o1.w = f3.y * inv;
        float* op = obase + (size_t)row * SEQN + col;
        *reinterpret_cast<float4*>(op) = o0;
        *reinterpret_cast<float4*>(op + 4) = o1;
    }
}

// ---------------------------------------------------------------------------
extern "C" void kernel_launch(void* const* d_in, const int* in_sizes, int n_in,
                              void* d_out, int out_size)
{
    const float* x = (const float*)d_in[0];    // [2,4096,256]
    const float* wmat = (const float*)d_in[1]; // [256,512]
    float* out = (float*)d_out;                // [2,8,4096,4096]

    dummy_kernel<<<1, 32>>>();                 // ncu capture-slot shim

    dim3 g1(TWOC / 64, (BATCH * SEQN) / 64);   // (8, 128)
    qkv_gemm_kernel<<<g1, 256>>>(x, wmat);

    prep_kernel<<<(BATCH * SEQN * 16) / 8, 256>>>();

    cudaFuncSetAttribute(attn_softmax_kernel,
                         cudaFuncAttributeMaxDynamicSharedMemorySize, SMEM_BYTES);
    dim3 g2(SEQN / ROWS, BATCH * NH);          // (256, 16)
    attn_softmax_kernel<<<g2, 256, SMEM_BYTES>>>(out);
}

// round 13
// speedup vs baseline: 1.9262x; 1.2309x over previous
#include <cuda_runtime.h>
#include <cuda_bf16.h>
#include <cuda_fp16.h>
#include <cstdint>

#define BATCH 2
#define SEQN 4096
#define CDIM 256
#define NH 8
#define DH 32
#define TWOC 512
#define SCALE 25.0f
// exp(25*d - 12) = exp2(d*25*log2e - 12*log2e)
#define EXP_A 36.06737602f
#define EXP_B 17.31234049f

#define ROWS 32            // q rows per CTA
#define CHUNK 128          // keys per chunk
#define NCHUNK (SEQN / CHUNK)

// -------- device scratch (no cudaMalloc allowed) --------
__device__ float g_qkv[BATCH * SEQN * TWOC];                       // 16 MB
__device__ __nv_bfloat16 g_qh[BATCH * NH * SEQN * DH];             // 4 MB
__device__ __nv_bfloat16 g_ql[BATCH * NH * SEQN * DH];             // 4 MB
__device__ __nv_bfloat16 g_kh[BATCH * NH * SEQN * DH];             // 4 MB
__device__ __nv_bfloat16 g_kl[BATCH * NH * SEQN * DH];             // 4 MB
__device__ __half g_e[(size_t)BATCH * NH * SEQN * SEQN];           // 536 MB fp16 exp scratch

// ---------------------------------------------------------------------------
// Dummy kernel: keeps ncu's fixed capture slot on the attn kernel.
// ---------------------------------------------------------------------------
__global__ void dummy_kernel() {}

// ---------------------------------------------------------------------------
// Kernel 1: qkv = x @ W   (M=8192, N=512, K=256)
// ---------------------------------------------------------------------------
__global__ __launch_bounds__(256) void qkv_gemm_kernel(
    const float* __restrict__ x, const float* __restrict__ w)
{
    __shared__ float As[64][17];
    __shared__ float Bs[16][65];

    const int tid = threadIdx.x;
    const int tx = tid & 15;
    const int ty = tid >> 4;
    const int rowBase = blockIdx.y * 64;
    const int colBase = blockIdx.x * 64;

    float acc[4][4];
#pragma unroll
    for (int i = 0; i < 4; i++)
#pragma unroll
        for (int j = 0; j < 4; j++) acc[i][j] = 0.f;

    for (int k0 = 0; k0 < CDIM; k0 += 16) {
        {
            const int r = tid >> 2;
            const int kk = (tid & 3) * 4;
            float4 a = *reinterpret_cast<const float4*>(
                x + (size_t)(rowBase + r) * CDIM + k0 + kk);
            As[r][kk + 0] = a.x; As[r][kk + 1] = a.y;
            As[r][kk + 2] = a.z; As[r][kk + 3] = a.w;
        }
        {
            const int r = tid >> 4;
            const int c = (tid & 15) * 4;
            float4 b = *reinterpret_cast<const float4*>(
                w + (size_t)(k0 + r) * TWOC + colBase + c);
            Bs[r][c + 0] = b.x; Bs[r][c + 1] = b.y;
            Bs[r][c + 2] = b.z; Bs[r][c + 3] = b.w;
        }
        __syncthreads();

#pragma unroll
        for (int kk = 0; kk < 16; kk++) {
            float ar[4], br[4];
#pragma unroll
            for (int i = 0; i < 4; i++) ar[i] = As[ty * 4 + i][kk];
#pragma unroll
            for (int j = 0; j < 4; j++) br[j] = Bs[kk][tx * 4 + j];
#pragma unroll
            for (int i = 0; i < 4; i++)
#pragma unroll
                for (int j = 0; j < 4; j++) acc[i][j] += ar[i] * br[j];
        }
        __syncthreads();
    }

#pragma unroll
    for (int i = 0; i < 4; i++) {
        float* orow = g_qkv + (size_t)(rowBase + ty * 4 + i) * TWOC + colBase + tx * 4;
#pragma unroll
        for (int j = 0; j < 4; j++) orow[j] = acc[i][j];
    }
}

// ---------------------------------------------------------------------------
// Kernel 1b: normalize + bf16 hi/lo split, layout [b*H+h][n][d]
// ---------------------------------------------------------------------------
__global__ __launch_bounds__(256) void prep_kernel()
{
    const int lane = threadIdx.x & 31;
    const int wid = blockIdx.x * 8 + (threadIdx.x >> 5);
    const int row = wid >> 4;
    const int rem = wid & 15;
    const int which = rem >> 3;
    const int h = rem & 7;

    float v = g_qkv[(size_t)row * TWOC + which * CDIM + h * DH + lane];
    float ss = v * v;
#pragma unroll
    for (int o = 16; o > 0; o >>= 1) ss += __shfl_xor_sync(0xffffffffu, ss, o);
    float nv = v / (sqrtf(ss) + 1e-8f);

    __nv_bfloat16 hi = __float2bfloat16_rn(nv);
    __nv_bfloat16 lo = __float2bfloat16_rn(nv - __bfloat162float(hi));

    const int b = row >> 12;
    const int n = row & 4095;
    const size_t dst = ((size_t)(b * NH + h) * SEQN + n) * DH + lane;
    if (which == 0) { g_qh[dst] = hi; g_ql[dst] = lo; }
    else            { g_kh[dst] = hi; g_kl[dst] = lo; }
}

// ---------------------------------------------------------------------------
// Kernel 2: scores + exp + rowsums with smem exp stage -> coalesced fp16
// scratch -> L2-hot readback -> rescale -> coalesced fp32 out.
// ROWS=32 (halves K L2 traffic), CHUNK=128, 2 barriers/chunk.
// ---------------------------------------------------------------------------

// smem byte offsets
#define OFF_KH   0u          // 2 bufs x 128 rows x 80 B = 20480
#define OFF_KL   20480u      // 20480
#define OFF_QH   40960u      // 32 rows x 80 B = 2560
#define OFF_QL   43520u      // 2560
#define OFF_STG  46080u      // 32 rows x 272 B = 8704
#define OFF_RS   54784u      // 32 floats
#define OFF_INV  54912u      // 32 floats
#define SMEM_BYTES 55040u
#define KBUF_STRIDE 10240u

__device__ __forceinline__ void cp_async16(uint32_t smem_dst, const void* gsrc) {
    asm volatile("cp.async.cg.shared.global [%0], [%1], 16;\n"
                 :: "r"(smem_dst), "l"(gsrc));
}
__device__ __forceinline__ void cp_commit() {
    asm volatile("cp.async.commit_group;\n");
}
template <int N>
__device__ __forceinline__ void cp_wait() {
    asm volatile("cp.async.wait_group %0;\n" :: "n"(N));
}

__device__ __forceinline__ void mma_bf16(float& d0, float& d1, float& d2, float& d3,
                                         const uint32_t* a,
                                         uint32_t b0, uint32_t b1) {
    asm volatile(
        "mma.sync.aligned.m16n8k16.row.col.f32.bf16.bf16.f32 "
        "{%0,%1,%2,%3}, {%4,%5,%6,%7}, {%8,%9}, {%0,%1,%2,%3};"
        : "+f"(d0), "+f"(d1), "+f"(d2), "+f"(d3)
        : "r"(a[0]), "r"(a[1]), "r"(a[2]), "r"(a[3]), "r"(b0), "r"(b1));
}

__global__ __launch_bounds__(256, 3) void attn_softmax_kernel(float* __restrict__ out)
{
    extern __shared__ char smem[];
    const uint32_t sbase = (uint32_t)__cvta_generic_to_shared(smem);

    const int tid = threadIdx.x;
    const int w = tid >> 5;               // warp 0..7
    const int lane = tid & 31;
    const int g = lane >> 2;              // row group 0..7
    const int t = lane & 3;               // quad id

    const int bh = blockIdx.y;            // 0..15
    const int qBase = blockIdx.x * ROWS;

    const __nv_bfloat16* qh = g_qh + ((size_t)bh * SEQN + qBase) * DH;
    const __nv_bfloat16* ql = g_ql + ((size_t)bh * SEQN + qBase) * DH;
    const __nv_bfloat16* kh = g_kh + (size_t)bh * SEQN * DH;
    const __nv_bfloat16* kl = g_kl + (size_t)bh * SEQN * DH;
    __half* ebase = g_e + ((size_t)bh * SEQN + qBase) * SEQN;

    // ---- Q tile into padded smem (32 rows x 32 halves, 80 B stride) ----
    for (int i = tid; i < ROWS * DH; i += 256) {
        const int r = i >> 5, d = i & 31;
        *reinterpret_cast<__nv_bfloat16*>(smem + OFF_QH + r * 80 + d * 2) = qh[i];
        *reinterpret_cast<__nv_bfloat16*>(smem + OFF_QL + r * 80 + d * 2) = ql[i];
    }
    if (tid < ROWS) *reinterpret_cast<float*>(smem + OFF_RS + tid * 4) = 0.f;

    // ---- issue chunk 0 (kh + kl): 128 rows x 4 segs = 512 tasks/plane ----
#pragma unroll
    for (int s = 0; s < 2; s++) {
        const int task = tid + 256 * s;
        const int r = task >> 2, seg = task & 3;
        cp_async16(sbase + OFF_KH + (uint32_t)(r * 80 + seg * 16),
                   (const char*)kh + r * 64 + seg * 16);
        cp_async16(sbase + OFF_KL + (uint32_t)(r * 80 + seg * 16),
                   (const char*)kl + r * 64 + seg * 16);
    }
    cp_commit();
    __syncthreads();

    // ---- A fragments (resident; two 16-row tiles) ----
    uint32_t aH[2][2][4], aL[2][2][4];     // [rt][ks][i]
#pragma unroll
    for (int rt = 0; rt < 2; rt++)
#pragma unroll
        for (int ks = 0; ks < 2; ks++) {
            const int c0 = ks * 16;
#pragma unroll
            for (int i = 0; i < 4; i++) {
                const int rr = rt * 16 + ((i & 1) ? g + 8 : g);
                const int cc = c0 + 2 * t + ((i >> 1) ? 8 : 0);
                aH[rt][ks][i] = *reinterpret_cast<const uint32_t*>(smem + OFF_QH + rr * 80 + cc * 2);
                aL[rt][ks][i] = *reinterpret_cast<const uint32_t*>(smem + OFF_QL + rr * 80 + cc * 2);
            }
        }

    float ps[4] = {0.f, 0.f, 0.f, 0.f};    // rowsum partials: [rt*2 + (0:row g,1:row g+8)]

    for (int c = 0; c < NCHUNK; c++) {
        cp_wait<0>();
        __syncthreads();      // chunk data visible; stage copy of c-1 done everywhere

        if (c + 1 < NCHUNK) {
            const uint32_t boff = ((c + 1) & 1) * KBUF_STRIDE;
            const char* khp = (const char*)kh + (size_t)(c + 1) * CHUNK * 64;
            const char* klp = (const char*)kl + (size_t)(c + 1) * CHUNK * 64;
#pragma unroll
            for (int s = 0; s < 2; s++) {
                const int task = tid + 256 * s;
                const int r = task >> 2, seg = task & 3;
                cp_async16(sbase + OFF_KH + boff + (uint32_t)(r * 80 + seg * 16),
                           khp + r * 64 + seg * 16);
                cp_async16(sbase + OFF_KL + boff + (uint32_t)(r * 80 + seg * 16),
                           klp + r * 64 + seg * 16);
            }
            cp_commit();
        }

        const uint32_t boff = (c & 1) * KBUF_STRIDE;
        const char* khS = smem + OFF_KH + boff;
        const char* klS = smem + OFF_KL + boff;

#pragma unroll
        for (int nt = 0; nt < 2; nt++) {
            const int kb = w * 16 + nt * 8 + g;   // key row within chunk
            uint32_t bH[2][2], bL[2][2];
#pragma unroll
            for (int ks = 0; ks < 2; ks++) {
                const int c0 = ks * 16;
                bH[ks][0] = *reinterpret_cast<const uint32_t*>(khS + kb * 80 + (c0 + 2 * t) * 2);
                bH[ks][1] = *reinterpret_cast<const uint32_t*>(khS + kb * 80 + (c0 + 2 * t + 8) * 2);
                bL[ks][0] = *reinterpret_cast<const uint32_t*>(klS + kb * 80 + (c0 + 2 * t) * 2);
                bL[ks][1] = *reinterpret_cast<const uint32_t*>(klS + kb * 80 + (c0 + 2 * t + 8) * 2);
            }

            const int col = w * 16 + nt * 8 + 2 * t;   // local col (even)
#pragma unroll
            for (int rt = 0; rt < 2; rt++) {
                float d0 = 0.f, d1 = 0.f, d2 = 0.f, d3 = 0.f;
#pragma unroll
                for (int ks = 0; ks < 2; ks++) {
                    mma_bf16(d0, d1, d2, d3, aH[rt][ks], bH[ks][0], bH[ks][1]);
                    mma_bf16(d0, d1, d2, d3, aL[rt][ks], bH[ks][0], bH[ks][1]);
                    mma_bf16(d0, d1, d2, d3, aH[rt][ks], bL[ks][0], bL[ks][1]);
                }
                float e0 = exp2f(fmaf(d0, EXP_A, -EXP_B));
                float e1 = exp2f(fmaf(d1, EXP_A, -EXP_B));
                float e2 = exp2f(fmaf(d2, EXP_A, -EXP_B));
                float e3 = exp2f(fmaf(d3, EXP_A, -EXP_B));
                const int r0 = rt * 16 + g, r1 = rt * 16 + 8 + g;
                *reinterpret_cast<__half2*>(smem + OFF_STG + r0 * 272 + col * 2) =
                    __floats2half2_rn(e0, e1);
                *reinterpret_cast<__half2*>(smem + OFF_STG + r1 * 272 + col * 2) =
                    __floats2half2_rn(e2, e3);
                ps[rt * 2 + 0] += e0 + e1;
                ps[rt * 2 + 1] += e2 + e3;
            }
        }
        __syncthreads();      // stage complete

        // ---- coalesced stage -> scratch (32 rows x 256 B, STG.128) ----
        __half* ecol = ebase + (size_t)c * CHUNK;
#pragma unroll
        for (int s = 0; s < 2; s++) {
            const int i = tid + 256 * s;
            const int r = i >> 4, seg = i & 15;
            uint4 v = *reinterpret_cast<const uint4*>(smem + OFF_STG + r * 272 + seg * 16);
            *reinterpret_cast<uint4*>(ecol + (size_t)r * SEQN + seg * 8) = v;
        }
    }

    // ---- rowsum reduce: quad shuffle + smem atomics ----
#pragma unroll
    for (int i = 0; i < 4; i++) {
        ps[i] += __shfl_xor_sync(0xffffffffu, ps[i], 1);
        ps[i] += __shfl_xor_sync(0xffffffffu, ps[i], 2);
    }
    if (t == 0) {
#pragma unroll
        for (int rt = 0; rt < 2; rt++) {
            atomicAdd(reinterpret_cast<float*>(smem + OFF_RS + (rt * 16 + g) * 4), ps[rt * 2]);
            atomicAdd(reinterpret_cast<float*>(smem + OFF_RS + (rt * 16 + 8 + g) * 4), ps[rt * 2 + 1]);
        }
    }
    __syncthreads();
    if (tid < ROWS) {
        float s = *reinterpret_cast<float*>(smem + OFF_RS + tid * 4);
        *reinterpret_cast<float*>(smem + OFF_INV + tid * 4) = 1.f / s;
    }
    __syncthreads();

    // ---- readback (L2-hot) + rescale + coalesced fp32 stores ----
    float* obase = out + ((size_t)bh * SEQN + qBase) * SEQN;
    for (int j = tid * 8; j < ROWS * SEQN; j += 2048) {
        const int row = j >> 12;
        const int col = j & 4095;
        uint4 v = *reinterpret_cast<const uint4*>(ebase + (size_t)row * SEQN + col);
        const float inv = *reinterpret_cast<float*>(smem + OFF_INV + row * 4);
        float2 f0 = __half22float2(*reinterpret_cast<__half2*>(&v.x));
        float2 f1 = __half22float2(*reinterpret_cast<__half2*>(&v.y));
        float2 f2 = __half22float2(*reinterpret_cast<__half2*>(&v.z));
        float2 f3 = __half22float2(*reinterpret_cast<__half2*>(&v.w));
        float4 o0, o1;
        o0.x = f0.x * inv; o0.y = f0.y * inv; o0.z = f1.x * inv; o0.w = f1.y * inv;
        o1.x = f2.x * inv; o1.y = f2.y * inv; o1.z = f3.x * inv; o1.w = f3.y * inv;
        float* op = obase + (size_t)row * SEQN + col;
        *reinterpret_cast<float4*>(op) = o0;
        *reinterpret_cast<float4*>(op + 4) = o1;
    }
}

// ---------------------------------------------------------------------------
extern "C" void kernel_launch(void* const* d_in, const int* in_sizes, int n_in,
                              void* d_out, int out_size)
{
    const float* x = (const float*)d_in[0];    // [2,4096,256]
    const float* wmat = (const float*)d_in[1]; // [256,512]
    float* out = (float*)d_out;                // [2,8,4096,4096]

    dummy_kernel<<<1, 32>>>();                 // ncu capture-slot shim

    dim3 g1(TWOC / 64, (BATCH * SEQN) / 64);   // (8, 128)
    qkv_gemm_kernel<<<g1, 256>>>(x, wmat);

    prep_kernel<<<(BATCH * SEQN * 16) / 8, 256>>>();

    cudaFuncSetAttribute(attn_softmax_kernel,
                         cudaFuncAttributeMaxDynamicSharedMemorySize, SMEM_BYTES);
    dim3 g2(SEQN / ROWS, BATCH * NH);          // (128, 16)
    attn_softmax_kernel<<<g2, 256, SMEM_BYTES>>>(out);
}

// round 14
// speedup vs baseline: 1.9887x; 1.0325x over previous
#include <cuda_runtime.h>
#include <cuda_bf16.h>
#include <cuda_fp16.h>
#include <cstdint>

#define BATCH 2
#define SEQN 4096
#define CDIM 256
#define NH 8
#define DH 32
#define TWOC 512
#define SCALE 25.0f
// exp(25*d - 12) = exp2(d*25*log2e - 12*log2e)
#define EXP_A 36.06737602f
#define EXP_B 17.31234049f

#define ROWS 32            // q rows per CTA
#define CHUNK 128          // keys per chunk
#define NCHUNK (SEQN / CHUNK)

// -------- device scratch (no cudaMalloc allowed) --------
__device__ float g_qkv[BATCH * SEQN * TWOC];                       // 16 MB
__device__ __nv_bfloat16 g_qh[BATCH * NH * SEQN * DH];             // 4 MB
__device__ __nv_bfloat16 g_ql[BATCH * NH * SEQN * DH];             // 4 MB
__device__ __nv_bfloat16 g_kh[BATCH * NH * SEQN * DH];             // 4 MB
__device__ __nv_bfloat16 g_kl[BATCH * NH * SEQN * DH];             // 4 MB

// ---------------------------------------------------------------------------
// Dummy kernel: keeps ncu's fixed capture slot on the attn kernel.
// ---------------------------------------------------------------------------
__global__ void dummy_kernel() {}

// ---------------------------------------------------------------------------
// Kernel 1: qkv = x @ W   (M=8192, N=512, K=256)
// ---------------------------------------------------------------------------
__global__ __launch_bounds__(256) void qkv_gemm_kernel(
    const float* __restrict__ x, const float* __restrict__ w)
{
    __shared__ float As[64][17];
    __shared__ float Bs[16][65];

    const int tid = threadIdx.x;
    const int tx = tid & 15;
    const int ty = tid >> 4;
    const int rowBase = blockIdx.y * 64;
    const int colBase = blockIdx.x * 64;

    float acc[4][4];
#pragma unroll
    for (int i = 0; i < 4; i++)
#pragma unroll
        for (int j = 0; j < 4; j++) acc[i][j] = 0.f;

    for (int k0 = 0; k0 < CDIM; k0 += 16) {
        {
            const int r = tid >> 2;
            const int kk = (tid & 3) * 4;
            float4 a = *reinterpret_cast<const float4*>(
                x + (size_t)(rowBase + r) * CDIM + k0 + kk);
            As[r][kk + 0] = a.x; As[r][kk + 1] = a.y;
            As[r][kk + 2] = a.z; As[r][kk + 3] = a.w;
        }
        {
            const int r = tid >> 4;
            const int c = (tid & 15) * 4;
            float4 b = *reinterpret_cast<const float4*>(
                w + (size_t)(k0 + r) * TWOC + colBase + c);
            Bs[r][c + 0] = b.x; Bs[r][c + 1] = b.y;
            Bs[r][c + 2] = b.z; Bs[r][c + 3] = b.w;
        }
        __syncthreads();

#pragma unroll
        for (int kk = 0; kk < 16; kk++) {
            float ar[4], br[4];
#pragma unroll
            for (int i = 0; i < 4; i++) ar[i] = As[ty * 4 + i][kk];
#pragma unroll
            for (int j = 0; j < 4; j++) br[j] = Bs[kk][tx * 4 + j];
#pragma unroll
            for (int i = 0; i < 4; i++)
#pragma unroll
                for (int j = 0; j < 4; j++) acc[i][j] += ar[i] * br[j];
        }
        __syncthreads();
    }

#pragma unroll
    for (int i = 0; i < 4; i++) {
        float* orow = g_qkv + (size_t)(rowBase + ty * 4 + i) * TWOC + colBase + tx * 4;
#pragma unroll
        for (int j = 0; j < 4; j++) orow[j] = acc[i][j];
    }
}

// ---------------------------------------------------------------------------
// Kernel 1b: normalize + bf16 hi/lo split, layout [b*H+h][n][d]
// ---------------------------------------------------------------------------
__global__ __launch_bounds__(256) void prep_kernel()
{
    const int lane = threadIdx.x & 31;
    const int wid = blockIdx.x * 8 + (threadIdx.x >> 5);
    const int row = wid >> 4;
    const int rem = wid & 15;
    const int which = rem >> 3;
    const int h = rem & 7;

    float v = g_qkv[(size_t)row * TWOC + which * CDIM + h * DH + lane];
    float ss = v * v;
#pragma unroll
    for (int o = 16; o > 0; o >>= 1) ss += __shfl_xor_sync(0xffffffffu, ss, o);
    float nv = v / (sqrtf(ss) + 1e-8f);

    __nv_bfloat16 hi = __float2bfloat16_rn(nv);
    __nv_bfloat16 lo = __float2bfloat16_rn(nv - __bfloat162float(hi));

    const int b = row >> 12;
    const int n = row & 4095;
    const size_t dst = ((size_t)(b * NH + h) * SEQN + n) * DH + lane;
    if (which == 0) { g_qh[dst] = hi; g_ql[dst] = lo; }
    else            { g_kh[dst] = hi; g_kl[dst] = lo; }
}

// ---------------------------------------------------------------------------
// Kernel 2: TWO-PASS RECOMPUTE, no gmem scratch.
//  Pass 1: 3-term MMA -> polynomial exp2 (FMA pipe) -> rowsums only.
//  Pass 2: same MMA -> MUFU exp2f * inv -> fp32 smem stage -> STG.128 out.
// ROWS=32, CHUNK=128, double-buffered cp.async K.
// ---------------------------------------------------------------------------

// smem byte offsets
#define OFF_KH   0u          // 2 bufs x 128 rows x 80 B = 20480
#define OFF_KL   20480u      // 20480
#define OFF_QH   40960u      // 32 rows x 80 B = 2560
#define OFF_QL   43520u      // 2560
#define OFF_STG  46080u      // 32 rows x 544 B fp32 stage = 17408
#define OFF_RS   63488u      // 32 floats
#define OFF_INV  63616u      // 32 floats
#define SMEM_BYTES 63744u
#define KBUF_STRIDE 10240u

__device__ __forceinline__ void cp_async16(uint32_t smem_dst, const void* gsrc) {
    asm volatile("cp.async.cg.shared.global [%0], [%1], 16;\n"
                 :: "r"(smem_dst), "l"(gsrc));
}
__device__ __forceinline__ void cp_commit() {
    asm volatile("cp.async.commit_group;\n");
}
template <int N>
__device__ __forceinline__ void cp_wait() {
    asm volatile("cp.async.wait_group %0;\n" :: "n"(N));
}

// degree-4 exp2 on the FMA pipe (pass-1 rowsums only); rel err ~1e-5
__device__ __forceinline__ float exp2_poly(float x) {
    float fl = floorf(x);
    float f = x - fl;
    float p = fmaf(f, 1.3697664e-2f, 5.1690354e-2f);
    p = fmaf(f, p, 2.4163845e-1f);
    p = fmaf(f, p, 6.9296668e-1f);
    p = fmaf(f, p, 1.0000038f);
    int e = (int)fl;
    return p * __int_as_float((e + 127) << 23);
}

__device__ __forceinline__ void mma_bf16(float& d0, float& d1, float& d2, float& d3,
                                         const uint32_t* a,
                                         uint32_t b0, uint32_t b1) {
    asm volatile(
        "mma.sync.aligned.m16n8k16.row.col.f32.bf16.bf16.f32 "
        "{%0,%1,%2,%3}, {%4,%5,%6,%7}, {%8,%9}, {%0,%1,%2,%3};"
        : "+f"(d0), "+f"(d1), "+f"(d2), "+f"(d3)
        : "r"(a[0]), "r"(a[1]), "r"(a[2]), "r"(a[3]), "r"(b0), "r"(b1));
}

__global__ __launch_bounds__(256, 3) void attn_softmax_kernel(float* __restrict__ out)
{
    extern __shared__ char smem[];
    const uint32_t sbase = (uint32_t)__cvta_generic_to_shared(smem);

    const int tid = threadIdx.x;
    const int w = tid >> 5;               // warp 0..7
    const int lane = tid & 31;
    const int g = lane >> 2;              // row group 0..7
    const int t = lane & 3;               // quad id

    const int bh = blockIdx.y;            // 0..15
    const int qBase = blockIdx.x * ROWS;

    const __nv_bfloat16* qh = g_qh + ((size_t)bh * SEQN + qBase) * DH;
    const __nv_bfloat16* ql = g_ql + ((size_t)bh * SEQN + qBase) * DH;
    const __nv_bfloat16* kh = g_kh + (size_t)bh * SEQN * DH;
    const __nv_bfloat16* kl = g_kl + (size_t)bh * SEQN * DH;

    // ---- Q tile into padded smem (32 rows x 32 halves, 80 B stride) ----
    for (int i = tid; i < ROWS * DH; i += 256) {
        const int r = i >> 5, d = i & 31;
        *reinterpret_cast<__nv_bfloat16*>(smem + OFF_QH + r * 80 + d * 2) = qh[i];
        *reinterpret_cast<__nv_bfloat16*>(smem + OFF_QL + r * 80 + d * 2) = ql[i];
    }
    if (tid < ROWS) *reinterpret_cast<float*>(smem + OFF_RS + tid * 4) = 0.f;

    auto prefetch = [&](int c) {
        const uint32_t boff = (uint32_t)(c & 1) * KBUF_STRIDE;
        const char* khp = (const char*)kh + (size_t)c * CHUNK * 64;
        const char* klp = (const char*)kl + (size_t)c * CHUNK * 64;
#pragma unroll
        for (int s = 0; s < 2; s++) {
            const int task = tid + 256 * s;
            const int r = task >> 2, seg = task & 3;
            cp_async16(sbase + OFF_KH + boff + (uint32_t)(r * 80 + seg * 16),
                       khp + r * 64 + seg * 16);
            cp_async16(sbase + OFF_KL + boff + (uint32_t)(r * 80 + seg * 16),
                       klp + r * 64 + seg * 16);
        }
        cp_commit();
    };

    prefetch(0);
    __syncthreads();

    // ---- A fragments (resident; two 16-row tiles) ----
    uint32_t aH[2][2][4], aL[2][2][4];     // [rt][ks][i]
#pragma unroll
    for (int rt = 0; rt < 2; rt++)
#pragma unroll
        for (int ks = 0; ks < 2; ks++) {
            const int c0 = ks * 16;
#pragma unroll
            for (int i = 0; i < 4; i++) {
                const int rr = rt * 16 + ((i & 1) ? g + 8 : g);
                const int cc = c0 + 2 * t + ((i >> 1) ? 8 : 0);
                aH[rt][ks][i] = *reinterpret_cast<const uint32_t*>(smem + OFF_QH + rr * 80 + cc * 2);
                aL[rt][ks][i] = *reinterpret_cast<const uint32_t*>(smem + OFF_QL + rr * 80 + cc * 2);
            }
        }

    float ps[4] = {0.f, 0.f, 0.f, 0.f};    // rowsum partials: [rt*2 + (0:row g,1:row g+8)]

    // =================== Pass 1: rowsums (poly exp2, FMA pipe) ===============
    for (int c = 0; c < NCHUNK; c++) {
        cp_wait<0>();
        __syncthreads();
        if (c + 1 < NCHUNK) prefetch(c + 1);

        const uint32_t boff = (c & 1) * KBUF_STRIDE;
        const char* khS = smem + OFF_KH + boff;
        const char* klS = smem + OFF_KL + boff;

#pragma unroll
        for (int nt = 0; nt < 2; nt++) {
            const int kb = w * 16 + nt * 8 + g;
            uint32_t bH[2][2], bL[2][2];
#pragma unroll
            for (int ks = 0; ks < 2; ks++) {
                const int c0 = ks * 16;
                bH[ks][0] = *reinterpret_cast<const uint32_t*>(khS + kb * 80 + (c0 + 2 * t) * 2);
                bH[ks][1] = *reinterpret_cast<const uint32_t*>(khS + kb * 80 + (c0 + 2 * t + 8) * 2);
                bL[ks][0] = *reinterpret_cast<const uint32_t*>(klS + kb * 80 + (c0 + 2 * t) * 2);
                bL[ks][1] = *reinterpret_cast<const uint32_t*>(klS + kb * 80 + (c0 + 2 * t + 8) * 2);
            }
#pragma unroll
            for (int rt = 0; rt < 2; rt++) {
                float d0 = 0.f, d1 = 0.f, d2 = 0.f, d3 = 0.f;
#pragma unroll
                for (int ks = 0; ks < 2; ks++) {
                    mma_bf16(d0, d1, d2, d3, aH[rt][ks], bH[ks][0], bH[ks][1]);
                    mma_bf16(d0, d1, d2, d3, aL[rt][ks], bH[ks][0], bH[ks][1]);
                    mma_bf16(d0, d1, d2, d3, aH[rt][ks], bL[ks][0], bL[ks][1]);
                }
                ps[rt * 2 + 0] += exp2_poly(fmaf(d0, EXP_A, -EXP_B))
                                + exp2_poly(fmaf(d1, EXP_A, -EXP_B));
                ps[rt * 2 + 1] += exp2_poly(fmaf(d2, EXP_A, -EXP_B))
                                + exp2_poly(fmaf(d3, EXP_A, -EXP_B));
            }
        }
    }

    // re-issue chunk 0 for pass 2 (buf0 free: all warps synced past chunk31 wait)
    prefetch(0);

    // ---- rowsum reduce: quad shuffle + smem atomics ----
#pragma unroll
    for (int i = 0; i < 4; i++) {
        ps[i] += __shfl_xor_sync(0xffffffffu, ps[i], 1);
        ps[i] += __shfl_xor_sync(0xffffffffu, ps[i], 2);
    }
    if (t == 0) {
#pragma unroll
        for (int rt = 0; rt < 2; rt++) {
            atomicAdd(reinterpret_cast<float*>(smem + OFF_RS + (rt * 16 + g) * 4), ps[rt * 2]);
            atomicAdd(reinterpret_cast<float*>(smem + OFF_RS + (rt * 16 + 8 + g) * 4), ps[rt * 2 + 1]);
        }
    }
    __syncthreads();
    if (tid < ROWS) {
        float s = *reinterpret_cast<float*>(smem + OFF_RS + tid * 4);
        *reinterpret_cast<float*>(smem + OFF_INV + tid * 4) = 1.f / s;
    }
    __syncthreads();

    float inv[2];
    inv[0] = *reinterpret_cast<float*>(smem + OFF_INV + g * 4);          // placeholder, re-read per rt below
    // per-thread inverses for its 4 owned rows
    float inv_r[4];
#pragma unroll
    for (int rt = 0; rt < 2; rt++) {
        inv_r[rt * 2 + 0] = *reinterpret_cast<float*>(smem + OFF_INV + (rt * 16 + g) * 4);
        inv_r[rt * 2 + 1] = *reinterpret_cast<float*>(smem + OFF_INV + (rt * 16 + 8 + g) * 4);
    }
    (void)inv;

    // =================== Pass 2: recompute + write (MUFU exp2f) ==============
    float* obase = out + ((size_t)bh * SEQN + qBase) * SEQN;
    for (int c = 0; c < NCHUNK; c++) {
        cp_wait<0>();
        __syncthreads();      // K chunk ready; prev sweep done everywhere
        if (c + 1 < NCHUNK) prefetch(c + 1);

        const uint32_t boff = (c & 1) * KBUF_STRIDE;
        const char* khS = smem + OFF_KH + boff;
        const char* klS = smem + OFF_KL + boff;

#pragma unroll
        for (int nt = 0; nt < 2; nt++) {
            const int kb = w * 16 + nt * 8 + g;
            uint32_t bH[2][2], bL[2][2];
#pragma unroll
            for (int ks = 0; ks < 2; ks++) {
                const int c0 = ks * 16;
                bH[ks][0] = *reinterpret_cast<const uint32_t*>(khS + kb * 80 + (c0 + 2 * t) * 2);
                bH[ks][1] = *reinterpret_cast<const uint32_t*>(khS + kb * 80 + (c0 + 2 * t + 8) * 2);
                bL[ks][0] = *reinterpret_cast<const uint32_t*>(klS + kb * 80 + (c0 + 2 * t) * 2);
                bL[ks][1] = *reinterpret_cast<const uint32_t*>(klS + kb * 80 + (c0 + 2 * t + 8) * 2);
            }

            const int col = w * 16 + nt * 8 + 2 * t;   // local col (even)
#pragma unroll
            for (int rt = 0; rt < 2; rt++) {
                float d0 = 0.f, d1 = 0.f, d2 = 0.f, d3 = 0.f;
#pragma unroll
                for (int ks = 0; ks < 2; ks++) {
                    mma_bf16(d0, d1, d2, d3, aH[rt][ks], bH[ks][0], bH[ks][1]);
                    mma_bf16(d0, d1, d2, d3, aL[rt][ks], bH[ks][0], bH[ks][1]);
                    mma_bf16(d0, d1, d2, d3, aH[rt][ks], bL[ks][0], bL[ks][1]);
                }
                float2 v0, v1;
                v0.x = exp2f(fmaf(d0, EXP_A, -EXP_B)) * inv_r[rt * 2 + 0];
                v0.y = exp2f(fmaf(d1, EXP_A, -EXP_B)) * inv_r[rt * 2 + 0];
                v1.x = exp2f(fmaf(d2, EXP_A, -EXP_B)) * inv_r[rt * 2 + 1];
                v1.y = exp2f(fmaf(d3, EXP_A, -EXP_B)) * inv_r[rt * 2 + 1];
                const int r0 = rt * 16 + g, r1 = rt * 16 + 8 + g;
                *reinterpret_cast<float2*>(smem + OFF_STG + r0 * 544 + col * 4) = v0;
                *reinterpret_cast<float2*>(smem + OFF_STG + r1 * 544 + col * 4) = v1;
            }
        }
        __syncthreads();      // stage complete

        // ---- coalesced stage -> out (32 rows x 512 B, STG.128) ----
        float* ocol = obase + (size_t)c * CHUNK;
#pragma unroll
        for (int s = 0; s < 4; s++) {
            const int i = tid + 256 * s;
            const int r = i >> 5, seg = i & 31;
            uint4 v = *reinterpret_cast<const uint4*>(smem + OFF_STG + r * 544 + seg * 16);
            *reinterpret_cast<uint4*>(ocol + (size_t)r * SEQN + seg * 4) = v;
        }
    }
}

// ---------------------------------------------------------------------------
extern "C" void kernel_launch(void* const* d_in, const int* in_sizes, int n_in,
                              void* d_out, int out_size)
{
    const float* x = (const float*)d_in[0];    // [2,4096,256]
    const float* wmat = (const float*)d_in[1]; // [256,512]
    float* out = (float*)d_out;                // [2,8,4096,4096]

    dummy_kernel<<<1, 32>>>();                 // ncu capture-slot shim

    dim3 g1(TWOC / 64, (BATCH * SEQN) / 64);   // (8, 128)
    qkv_gemm_kernel<<<g1, 256>>>(x, wmat);

    prep_kernel<<<(BATCH * SEQN * 16) / 8, 256>>>();

    cudaFuncSetAttribute(attn_softmax_kernel,
                         cudaFuncAttributeMaxDynamicSharedMemorySize, SMEM_BYTES);
    dim3 g2(SEQN / ROWS, BATCH * NH);          // (128, 16)
    attn_softmax_kernel<<<g2, 256, SMEM_BYTES>>>(out);
}

// round 16
// speedup vs baseline: 2.1251x; 1.0686x over previous
#include <cuda_runtime.h>
#include <cuda_bf16.h>
#include <cuda_fp16.h>
#include <cstdint>

#define BATCH 2
#define SEQN 4096
#define CDIM 256
#define NH 8
#define DH 32
#define TWOC 512
#define SCALE 25.0f
// exp(25*d - 12) = exp2(d*25*log2e - 12*log2e)
#define EXP_A 36.06737602f
#define EXP_B 17.31234049f

#define ROWS 64            // q rows per CTA
#define CHUNK 128          // keys per chunk
#define NCHUNK (SEQN / CHUNK)

// -------- device scratch (no cudaMalloc allowed) --------
__device__ float g_qkv[BATCH * SEQN * TWOC];                       // 16 MB
__device__ __nv_bfloat16 g_qh[BATCH * NH * SEQN * DH];             // 4 MB
__device__ __nv_bfloat16 g_ql[BATCH * NH * SEQN * DH];             // 4 MB
__device__ __nv_bfloat16 g_kh[BATCH * NH * SEQN * DH];             // 4 MB
__device__ __nv_bfloat16 g_kl[BATCH * NH * SEQN * DH];             // 4 MB

// ---------------------------------------------------------------------------
// Dummy kernel: keeps ncu's fixed capture slot on the attn kernel.
// ---------------------------------------------------------------------------
__global__ void dummy_kernel() {}

// ---------------------------------------------------------------------------
// Kernel 1: qkv = x @ W   (M=8192, N=512, K=256)
// ---------------------------------------------------------------------------
__global__ __launch_bounds__(256) void qkv_gemm_kernel(
    const float* __restrict__ x, const float* __restrict__ w)
{
    __shared__ float As[64][17];
    __shared__ float Bs[16][65];

    const int tid = threadIdx.x;
    const int tx = tid & 15;
    const int ty = tid >> 4;
    const int rowBase = blockIdx.y * 64;
    const int colBase = blockIdx.x * 64;

    float acc[4][4];
#pragma unroll
    for (int i = 0; i < 4; i++)
#pragma unroll
        for (int j = 0; j < 4; j++) acc[i][j] = 0.f;

    for (int k0 = 0; k0 < CDIM; k0 += 16) {
        {
            const int r = tid >> 2;
            const int kk = (tid & 3) * 4;
            float4 a = *reinterpret_cast<const float4*>(
                x + (size_t)(rowBase + r) * CDIM + k0 + kk);
            As[r][kk + 0] = a.x; As[r][kk + 1] = a.y;
            As[r][kk + 2] = a.z; As[r][kk + 3] = a.w;
        }
        {
            const int r = tid >> 4;
            const int c = (tid & 15) * 4;
            float4 b = *reinterpret_cast<const float4*>(
                w + (size_t)(k0 + r) * TWOC + colBase + c);
            Bs[r][c + 0] = b.x; Bs[r][c + 1] = b.y;
            Bs[r][c + 2] = b.z; Bs[r][c + 3] = b.w;
        }
        __syncthreads();

#pragma unroll
        for (int kk = 0; kk < 16; kk++) {
            float ar[4], br[4];
#pragma unroll
            for (int i = 0; i < 4; i++) ar[i] = As[ty * 4 + i][kk];
#pragma unroll
            for (int j = 0; j < 4; j++) br[j] = Bs[kk][tx * 4 + j];
#pragma unroll
            for (int i = 0; i < 4; i++)
#pragma unroll
                for (int j = 0; j < 4; j++) acc[i][j] += ar[i] * br[j];
        }
        __syncthreads();
    }

#pragma unroll
    for (int i = 0; i < 4; i++) {
        float* orow = g_qkv + (size_t)(rowBase + ty * 4 + i) * TWOC + colBase + tx * 4;
#pragma unroll
        for (int j = 0; j < 4; j++) orow[j] = acc[i][j];
    }
}

// ---------------------------------------------------------------------------
// Kernel 1b: normalize + bf16 hi/lo split, layout [b*H+h][n][d]
// ---------------------------------------------------------------------------
__global__ __launch_bounds__(256) void prep_kernel()
{
    const int lane = threadIdx.x & 31;
    const int wid = blockIdx.x * 8 + (threadIdx.x >> 5);
    const int row = wid >> 4;
    const int rem = wid & 15;
    const int which = rem >> 3;
    const int h = rem & 7;

    float v = g_qkv[(size_t)row * TWOC + which * CDIM + h * DH + lane];
    float ss = v * v;
#pragma unroll
    for (int o = 16; o > 0; o >>= 1) ss += __shfl_xor_sync(0xffffffffu, ss, o);
    float nv = v / (sqrtf(ss) + 1e-8f);

    __nv_bfloat16 hi = __float2bfloat16_rn(nv);
    __nv_bfloat16 lo = __float2bfloat16_rn(nv - __bfloat162float(hi));

    const int b = row >> 12;
    const int n = row & 4095;
    const size_t dst = ((size_t)(b * NH + h) * SEQN + n) * DH + lane;
    if (which == 0) { g_qh[dst] = hi; g_ql[dst] = lo; }
    else            { g_kh[dst] = hi; g_kl[dst] = lo; }
}

// ---------------------------------------------------------------------------
// Kernel 2: TWO-PASS RECOMPUTE, ROWS=64 (halved K L2 traffic, 2x B-frag
// reuse), CHUNK=128, 2 CTAs/SM.
//  Pass 1: 3-term MMA -> polynomial exp2 (FMA pipe) -> rowsums only.
//  Pass 2: same MMA -> MUFU exp2f with folded 1/rowsum -> fp32 smem stage
//          -> STG.128 out.
// ---------------------------------------------------------------------------

// smem byte offsets
#define OFF_KH   0u          // 2 bufs x 128 rows x 80 B = 20480
#define OFF_KL   20480u      // 20480
#define OFF_QH   40960u      // 64 rows x 80 B = 5120
#define OFF_QL   46080u      // 5120
#define OFF_STG  51200u      // 64 rows x 544 B fp32 stage = 34816
#define OFF_RS   86016u      // 64 floats
#define OFF_INV  86272u      // 64 floats
#define SMEM_BYTES 86528u
#define KBUF_STRIDE 10240u

__device__ __forceinline__ void cp_async16(uint32_t smem_dst, const void* gsrc) {
    asm volatile("cp.async.cg.shared.global [%0], [%1], 16;\n"
                 :: "r"(smem_dst), "l"(gsrc));
}
__device__ __forceinline__ void cp_commit() {
    asm volatile("cp.async.commit_group;\n");
}
template <int N>
__device__ __forceinline__ void cp_wait() {
    asm volatile("cp.async.wait_group %0;\n" :: "n"(N));
}

// degree-4 exp2 on the FMA pipe (pass-1 rowsums only); rel err ~1e-5
__device__ __forceinline__ float exp2_poly(float x) {
    float fl = floorf(x);
    float f = x - fl;
    float p = fmaf(f, 1.3697664e-2f, 5.1690354e-2f);
    p = fmaf(f, p, 2.4163845e-1f);
    p = fmaf(f, p, 6.9296668e-1f);
    p = fmaf(f, p, 1.0000038f);
    int e = (int)fl;
    return p * __int_as_float((e + 127) << 23);
}

__device__ __forceinline__ void mma_bf16(float& d0, float& d1, float& d2, float& d3,
                                         const uint32_t* a,
                                         uint32_t b0, uint32_t b1) {
    asm volatile(
        "mma.sync.aligned.m16n8k16.row.col.f32.bf16.bf16.f32 "
        "{%0,%1,%2,%3}, {%4,%5,%6,%7}, {%8,%9}, {%0,%1,%2,%3};"
        : "+f"(d0), "+f"(d1), "+f"(d2), "+f"(d3)
        : "r"(a[0]), "r"(a[1]), "r"(a[2]), "r"(a[3]), "r"(b0), "r"(b1));
}

__global__ __launch_bounds__(256, 2) void attn_softmax_kernel(float* __restrict__ out)
{
    extern __shared__ char smem[];
    const uint32_t sbase = (uint32_t)__cvta_generic_to_shared(smem);

    const int tid = threadIdx.x;
    const int w = tid >> 5;               // warp 0..7
    const int lane = tid & 31;
    const int g = lane >> 2;              // row group 0..7
    const int t = lane & 3;               // quad id

    const int bh = blockIdx.y;            // 0..15
    const int qBase = blockIdx.x * ROWS;

    const __nv_bfloat16* qh = g_qh + ((size_t)bh * SEQN + qBase) * DH;
    const __nv_bfloat16* ql = g_ql + ((size_t)bh * SEQN + qBase) * DH;
    const __nv_bfloat16* kh = g_kh + (size_t)bh * SEQN * DH;
    const __nv_bfloat16* kl = g_kl + (size_t)bh * SEQN * DH;

    // ---- Q tile into padded smem (64 rows x 32 halves, 80 B stride) ----
    for (int i = tid; i < ROWS * DH; i += 256) {
        const int r = i >> 5, d = i & 31;
        *reinterpret_cast<__nv_bfloat16*>(smem + OFF_QH + r * 80 + d * 2) = qh[i];
        *reinterpret_cast<__nv_bfloat16*>(smem + OFF_QL + r * 80 + d * 2) = ql[i];
    }
    if (tid < ROWS) *reinterpret_cast<float*>(smem + OFF_RS + tid * 4) = 0.f;

    auto prefetch = [&](int c) {
        const uint32_t boff = (uint32_t)(c & 1) * KBUF_STRIDE;
        const char* khp = (const char*)kh + (size_t)c * CHUNK * 64;
        const char* klp = (const char*)kl + (size_t)c * CHUNK * 64;
#pragma unroll
        for (int s = 0; s < 2; s++) {
            const int task = tid + 256 * s;
            const int r = task >> 2, seg = task & 3;
            cp_async16(sbase + OFF_KH + boff + (uint32_t)(r * 80 + seg * 16),
                       khp + r * 64 + seg * 16);
            cp_async16(sbase + OFF_KL + boff + (uint32_t)(r * 80 + seg * 16),
                       klp + r * 64 + seg * 16);
        }
        cp_commit();
    };

    prefetch(0);
    __syncthreads();

    // ---- A fragments (resident; four 16-row tiles) ----
    uint32_t aH[4][2][4], aL[4][2][4];     // [rt][ks][i]
#pragma unroll
    for (int rt = 0; rt < 4; rt++)
#pragma unroll
        for (int ks = 0; ks < 2; ks++) {
            const int c0 = ks * 16;
#pragma unroll
            for (int i = 0; i < 4; i++) {
                const int rr = rt * 16 + ((i & 1) ? g + 8 : g);
                const int cc = c0 + 2 * t + ((i >> 1) ? 8 : 0);
                aH[rt][ks][i] = *reinterpret_cast<const uint32_t*>(smem + OFF_QH + rr * 80 + cc * 2);
                aL[rt][ks][i] = *reinterpret_cast<const uint32_t*>(smem + OFF_QL + rr * 80 + cc * 2);
            }
        }

    float ps[8] = {0.f, 0.f, 0.f, 0.f, 0.f, 0.f, 0.f, 0.f};   // [rt*2 + half]

    // =================== Pass 1: rowsums (poly exp2, FMA pipe) ===============
    for (int c = 0; c < NCHUNK; c++) {
        cp_wait<0>();
        __syncthreads();
        if (c + 1 < NCHUNK) prefetch(c + 1);

        const uint32_t boff = (c & 1) * KBUF_STRIDE;
        const char* khS = smem + OFF_KH + boff;
        const char* klS = smem + OFF_KL + boff;

#pragma unroll
        for (int nt = 0; nt < 2; nt++) {
            const int kb = w * 16 + nt * 8 + g;
            uint32_t bH[2][2], bL[2][2];
#pragma unroll
            for (int ks = 0; ks < 2; ks++) {
                const int c0 = ks * 16;
                bH[ks][0] = *reinterpret_cast<const uint32_t*>(khS + kb * 80 + (c0 + 2 * t) * 2);
                bH[ks][1] = *reinterpret_cast<const uint32_t*>(khS + kb * 80 + (c0 + 2 * t + 8) * 2);
                bL[ks][0] = *reinterpret_cast<const uint32_t*>(klS + kb * 80 + (c0 + 2 * t) * 2);
                bL[ks][1] = *reinterpret_cast<const uint32_t*>(klS + kb * 80 + (c0 + 2 * t + 8) * 2);
            }
#pragma unroll
            for (int rt = 0; rt < 4; rt++) {
                float d0 = 0.f, d1 = 0.f, d2 = 0.f, d3 = 0.f;
#pragma unroll
                for (int ks = 0; ks < 2; ks++) {
                    mma_bf16(d0, d1, d2, d3, aH[rt][ks], bH[ks][0], bH[ks][1]);
                    mma_bf16(d0, d1, d2, d3, aL[rt][ks], bH[ks][0], bH[ks][1]);
                    mma_bf16(d0, d1, d2, d3, aH[rt][ks], bL[ks][0], bL[ks][1]);
                }
                ps[rt * 2 + 0] += exp2_poly(fmaf(d0, EXP_A, -EXP_B))
                                + exp2_poly(fmaf(d1, EXP_A, -EXP_B));
                ps[rt * 2 + 1] += exp2_poly(fmaf(d2, EXP_A, -EXP_B))
                                + exp2_poly(fmaf(d3, EXP_A, -EXP_B));
            }
        }
    }

    // re-issue chunk 0 for pass 2 (buf0 free: all warps synced past last wait)
    prefetch(0);

    // ---- rowsum reduce: quad shuffle + smem atomics ----
#pragma unroll
    for (int i = 0; i < 8; i++) {
        ps[i] += __shfl_xor_sync(0xffffffffu, ps[i], 1);
        ps[i] += __shfl_xor_sync(0xffffffffu, ps[i], 2);
    }
    if (t == 0) {
#pragma unroll
        for (int rt = 0; rt < 4; rt++) {
            atomicAdd(reinterpret_cast<float*>(smem + OFF_RS + (rt * 16 + g) * 4), ps[rt * 2]);
            atomicAdd(reinterpret_cast<float*>(smem + OFF_RS + (rt * 16 + 8 + g) * 4), ps[rt * 2 + 1]);
        }
    }
    __syncthreads();
    if (tid < ROWS) {
        float s = *reinterpret_cast<float*>(smem + OFF_RS + tid * 4);
        *reinterpret_cast<float*>(smem + OFF_INV + tid * 4) = 1.f / s;
    }
    __syncthreads();

    // per-thread folded exponent offsets: c_r = log2(inv_row) - EXP_B
    float cfold[8];
#pragma unroll
    for (int rt = 0; rt < 4; rt++) {
        float i0 = *reinterpret_cast<float*>(smem + OFF_INV + (rt * 16 + g) * 4);
        float i1 = *reinterpret_cast<float*>(smem + OFF_INV + (rt * 16 + 8 + g) * 4);
        cfold[rt * 2 + 0] = log2f(i0) - EXP_B;
        cfold[rt * 2 + 1] = log2f(i1) - EXP_B;
    }

    // =================== Pass 2: recompute + write (MUFU exp2f) ==============
    float* obase = out + ((size_t)bh * SEQN + qBase) * SEQN;
    for (int c = 0; c < NCHUNK; c++) {
        cp_wait<0>();
        __syncthreads();      // K chunk ready; prev sweep done everywhere
        if (c + 1 < NCHUNK) prefetch(c + 1);

        const uint32_t boff = (c & 1) * KBUF_STRIDE;
        const char* khS = smem + OFF_KH + boff;
        const char* klS = smem + OFF_KL + boff;

#pragma unroll
        for (int nt = 0; nt < 2; nt++) {
            const int kb = w * 16 + nt * 8 + g;
            uint32_t bH[2][2], bL[2][2];
#pragma unroll
            for (int ks = 0; ks < 2; ks++) {
                const int c0 = ks * 16;
                bH[ks][0] = *reinterpret_cast<const uint32_t*>(khS + kb * 80 + (c0 + 2 * t) * 2);
                bH[ks][1] = *reinterpret_cast<const uint32_t*>(khS + kb * 80 + (c0 + 2 * t + 8) * 2);
                bL[ks][0] = *reinterpret_cast<const uint32_t*>(klS + kb * 80 + (c0 + 2 * t) * 2);
                bL[ks][1] = *reinterpret_cast<const uint32_t*>(klS + kb * 80 + (c0 + 2 * t + 8) * 2);
            }

            const int col = w * 16 + nt * 8 + 2 * t;   // local col (even)
#pragma unroll
            for (int rt = 0; rt < 4; rt++) {
                float d0 = 0.f, d1 = 0.f, d2 = 0.f, d3 = 0.f;
#pragma unroll
                for (int ks = 0; ks < 2; ks++) {
                    mma_bf16(d0, d1, d2, d3, aH[rt][ks], bH[ks][0], bH[ks][1]);
                    mma_bf16(d0, d1, d2, d3, aL[rt][ks], bH[ks][0], bH[ks][1]);
                    mma_bf16(d0, d1, d2, d3, aH[rt][ks], bL[ks][0], bL[ks][1]);
                }
                float2 v0, v1;
                v0.x = exp2f(fmaf(d0, EXP_A, cfold[rt * 2 + 0]));
                v0.y = exp2f(fmaf(d1, EXP_A, cfold[rt * 2 + 0]));
                v1.x = exp2f(fmaf(d2, EXP_A, cfold[rt * 2 + 1]));
                v1.y = exp2f(fmaf(d3, EXP_A, cfold[rt * 2 + 1]));
                const int r0 = rt * 16 + g, r1 = rt * 16 + 8 + g;
                *reinterpret_cast<float2*>(smem + OFF_STG + r0 * 544 + col * 4) = v0;
                *reinterpret_cast<float2*>(smem + OFF_STG + r1 * 544 + col * 4) = v1;
            }
        }
        __syncthreads();      // stage complete

        // ---- coalesced stage -> out (64 rows x 512 B, STG.128) ----
        float* ocol = obase + (size_t)c * CHUNK;
#pragma unroll
        for (int s = 0; s < 8; s++) {
            const int i = tid + 256 * s;
            const int r = i >> 5, seg = i & 31;
            uint4 v = *reinterpret_cast<const uint4*>(smem + OFF_STG + r * 544 + seg * 16);
            *reinterpret_cast<uint4*>(ocol + (size_t)r * SEQN + seg * 4) = v;
        }
    }
}

// ---------------------------------------------------------------------------
extern "C" void kernel_launch(void* const* d_in, const int* in_sizes, int n_in,
                              void* d_out, int out_size)
{
    const float* x = (const float*)d_in[0];    // [2,4096,256]
    const float* wmat = (const float*)d_in[1]; // [256,512]
    float* out = (float*)d_out;                // [2,8,4096,4096]

    dummy_kernel<<<1, 32>>>();                 // ncu capture-slot shim

    dim3 g1(TWOC / 64, (BATCH * SEQN) / 64);   // (8, 128)
    qkv_gemm_kernel<<<g1, 256>>>(x, wmat);

    prep_kernel<<<(BATCH * SEQN * 16) / 8, 256>>>();

    cudaFuncSetAttribute(attn_softmax_kernel,
                         cudaFuncAttributeMaxDynamicSharedMemorySize, SMEM_BYTES);
    dim3 g2(SEQN / ROWS, BATCH * NH);          // (64, 16)
    attn_softmax_kernel<<<g2, 256, SMEM_BYTES>>>(out);
}

// round 17
// speedup vs baseline: 2.1947x; 1.0327x over previous
#include <cuda_runtime.h>
#include <cuda_bf16.h>
#include <cuda_fp16.h>
#include <cstdint>

#define BATCH 2
#define SEQN 4096
#define CDIM 256
#define NH 8
#define DH 32
#define TWOC 512
#define SCALE 25.0f
// exp(25*d - 12) = exp2(d*25*log2e - 12*log2e)
#define EXP_A 36.06737602f
#define EXP_B 17.31234049f

#define ROWS 64            // q rows per CTA
#define CHUNK 128          // keys per chunk
#define NCHUNK (SEQN / CHUNK)

// -------- device scratch (no cudaMalloc allowed) --------
__device__ float g_qkv[BATCH * SEQN * TWOC];                       // 16 MB
__device__ __nv_bfloat16 g_qh[BATCH * NH * SEQN * DH];             // 4 MB
__device__ __nv_bfloat16 g_ql[BATCH * NH * SEQN * DH];             // 4 MB
__device__ __nv_bfloat16 g_kh[BATCH * NH * SEQN * DH];             // 4 MB
__device__ __nv_bfloat16 g_kl[BATCH * NH * SEQN * DH];             // 4 MB

// ---------------------------------------------------------------------------
// Dummy kernel: keeps ncu's fixed capture slot on the attn kernel.
// ---------------------------------------------------------------------------
__global__ void dummy_kernel() {}

// ---------------------------------------------------------------------------
// Kernel 1: qkv = x @ W   (M=8192, N=512, K=256)
// ---------------------------------------------------------------------------
__global__ __launch_bounds__(256) void qkv_gemm_kernel(
    const float* __restrict__ x, const float* __restrict__ w)
{
    __shared__ float As[64][17];
    __shared__ float Bs[16][65];

    const int tid = threadIdx.x;
    const int tx = tid & 15;
    const int ty = tid >> 4;
    const int rowBase = blockIdx.y * 64;
    const int colBase = blockIdx.x * 64;

    float acc[4][4];
#pragma unroll
    for (int i = 0; i < 4; i++)
#pragma unroll
        for (int j = 0; j < 4; j++) acc[i][j] = 0.f;

    for (int k0 = 0; k0 < CDIM; k0 += 16) {
        {
            const int r = tid >> 2;
            const int kk = (tid & 3) * 4;
            float4 a = *reinterpret_cast<const float4*>(
                x + (size_t)(rowBase + r) * CDIM + k0 + kk);
            As[r][kk + 0] = a.x; As[r][kk + 1] = a.y;
            As[r][kk + 2] = a.z; As[r][kk + 3] = a.w;
        }
        {
            const int r = tid >> 4;
            const int c = (tid & 15) * 4;
            float4 b = *reinterpret_cast<const float4*>(
                w + (size_t)(k0 + r) * TWOC + colBase + c);
            Bs[r][c + 0] = b.x; Bs[r][c + 1] = b.y;
            Bs[r][c + 2] = b.z; Bs[r][c + 3] = b.w;
        }
        __syncthreads();

#pragma unroll
        for (int kk = 0; kk < 16; kk++) {
            float ar[4], br[4];
#pragma unroll
            for (int i = 0; i < 4; i++) ar[i] = As[ty * 4 + i][kk];
#pragma unroll
            for (int j = 0; j < 4; j++) br[j] = Bs[kk][tx * 4 + j];
#pragma unroll
            for (int i = 0; i < 4; i++)
#pragma unroll
                for (int j = 0; j < 4; j++) acc[i][j] += ar[i] * br[j];
        }
        __syncthreads();
    }

#pragma unroll
    for (int i = 0; i < 4; i++) {
        float* orow = g_qkv + (size_t)(rowBase + ty * 4 + i) * TWOC + colBase + tx * 4;
#pragma unroll
        for (int j = 0; j < 4; j++) orow[j] = acc[i][j];
    }
}

// ---------------------------------------------------------------------------
// Kernel 1b: normalize + bf16 hi/lo split, layout [b*H+h][n][d]
// ---------------------------------------------------------------------------
__global__ __launch_bounds__(256) void prep_kernel()
{
    const int lane = threadIdx.x & 31;
    const int wid = blockIdx.x * 8 + (threadIdx.x >> 5);
    const int row = wid >> 4;
    const int rem = wid & 15;
    const int which = rem >> 3;
    const int h = rem & 7;

    float v = g_qkv[(size_t)row * TWOC + which * CDIM + h * DH + lane];
    float ss = v * v;
#pragma unroll
    for (int o = 16; o > 0; o >>= 1) ss += __shfl_xor_sync(0xffffffffu, ss, o);
    float nv = v / (sqrtf(ss) + 1e-8f);

    __nv_bfloat16 hi = __float2bfloat16_rn(nv);
    __nv_bfloat16 lo = __float2bfloat16_rn(nv - __bfloat162float(hi));

    const int b = row >> 12;
    const int n = row & 4095;
    const size_t dst = ((size_t)(b * NH + h) * SEQN + n) * DH + lane;
    if (which == 0) { g_qh[dst] = hi; g_ql[dst] = lo; }
    else            { g_kh[dst] = hi; g_kl[dst] = lo; }
}

// ---------------------------------------------------------------------------
// Kernel 2: TWO-PASS RECOMPUTE, ROWS=64, CHUNK=128, 2 CTAs/SM.
//  Pass 1: 3-term MMA -> MUFU exp2f -> rowsums only (poly removed: kernel is
//          issue-bound, MUFU total load across both passes is only ~126us).
//  Pass 2: same MMA -> MUFU exp2f with folded 1/rowsum -> fp32 smem stage
//          -> STG.128 out.
// ---------------------------------------------------------------------------

// smem byte offsets
#define OFF_KH   0u          // 2 bufs x 128 rows x 80 B = 20480
#define OFF_KL   20480u      // 20480
#define OFF_QH   40960u      // 64 rows x 80 B = 5120
#define OFF_QL   46080u      // 5120
#define OFF_STG  51200u      // 64 rows x 544 B fp32 stage = 34816
#define OFF_RS   86016u      // 64 floats
#define OFF_INV  86272u      // 64 floats
#define SMEM_BYTES 86528u
#define KBUF_STRIDE 10240u

__device__ __forceinline__ void cp_async16(uint32_t smem_dst, const void* gsrc) {
    asm volatile("cp.async.cg.shared.global [%0], [%1], 16;\n"
                 :: "r"(smem_dst), "l"(gsrc));
}
__device__ __forceinline__ void cp_commit() {
    asm volatile("cp.async.commit_group;\n");
}
template <int N>
__device__ __forceinline__ void cp_wait() {
    asm volatile("cp.async.wait_group %0;\n" :: "n"(N));
}

__device__ __forceinline__ void mma_bf16(float& d0, float& d1, float& d2, float& d3,
                                         const uint32_t* a,
                                         uint32_t b0, uint32_t b1) {
    asm volatile(
        "mma.sync.aligned.m16n8k16.row.col.f32.bf16.bf16.f32 "
        "{%0,%1,%2,%3}, {%4,%5,%6,%7}, {%8,%9}, {%0,%1,%2,%3};"
        : "+f"(d0), "+f"(d1), "+f"(d2), "+f"(d3)
        : "r"(a[0]), "r"(a[1]), "r"(a[2]), "r"(a[3]), "r"(b0), "r"(b1));
}

__global__ __launch_bounds__(256, 2) void attn_softmax_kernel(float* __restrict__ out)
{
    extern __shared__ char smem[];
    const uint32_t sbase = (uint32_t)__cvta_generic_to_shared(smem);

    const int tid = threadIdx.x;
    const int w = tid >> 5;               // warp 0..7
    const int lane = tid & 31;
    const int g = lane >> 2;              // row group 0..7
    const int t = lane & 3;               // quad id

    const int bh = blockIdx.y;            // 0..15
    const int qBase = blockIdx.x * ROWS;

    const __nv_bfloat16* qh = g_qh + ((size_t)bh * SEQN + qBase) * DH;
    const __nv_bfloat16* ql = g_ql + ((size_t)bh * SEQN + qBase) * DH;
    const __nv_bfloat16* kh = g_kh + (size_t)bh * SEQN * DH;
    const __nv_bfloat16* kl = g_kl + (size_t)bh * SEQN * DH;

    // ---- Q tile into padded smem (64 rows x 32 halves, 80 B stride) ----
    for (int i = tid; i < ROWS * DH; i += 256) {
        const int r = i >> 5, d = i & 31;
        *reinterpret_cast<__nv_bfloat16*>(smem + OFF_QH + r * 80 + d * 2) = qh[i];
        *reinterpret_cast<__nv_bfloat16*>(smem + OFF_QL + r * 80 + d * 2) = ql[i];
    }
    if (tid < ROWS) *reinterpret_cast<float*>(smem + OFF_RS + tid * 4) = 0.f;

    auto prefetch = [&](int c) {
        const uint32_t boff = (uint32_t)(c & 1) * KBUF_STRIDE;
        const char* khp = (const char*)kh + (size_t)c * CHUNK * 64;
        const char* klp = (const char*)kl + (size_t)c * CHUNK * 64;
#pragma unroll
        for (int s = 0; s < 2; s++) {
            const int task = tid + 256 * s;
            const int r = task >> 2, seg = task & 3;
            cp_async16(sbase + OFF_KH + boff + (uint32_t)(r * 80 + seg * 16),
                       khp + r * 64 + seg * 16);
            cp_async16(sbase + OFF_KL + boff + (uint32_t)(r * 80 + seg * 16),
                       klp + r * 64 + seg * 16);
        }
        cp_commit();
    };

    prefetch(0);
    __syncthreads();

    // ---- A fragments (resident; four 16-row tiles) ----
    uint32_t aH[4][2][4], aL[4][2][4];     // [rt][ks][i]
#pragma unroll
    for (int rt = 0; rt < 4; rt++)
#pragma unroll
        for (int ks = 0; ks < 2; ks++) {
            const int c0 = ks * 16;
#pragma unroll
            for (int i = 0; i < 4; i++) {
                const int rr = rt * 16 + ((i & 1) ? g + 8 : g);
                const int cc = c0 + 2 * t + ((i >> 1) ? 8 : 0);
                aH[rt][ks][i] = *reinterpret_cast<const uint32_t*>(smem + OFF_QH + rr * 80 + cc * 2);
                aL[rt][ks][i] = *reinterpret_cast<const uint32_t*>(smem + OFF_QL + rr * 80 + cc * 2);
            }
        }

    float ps[8] = {0.f, 0.f, 0.f, 0.f, 0.f, 0.f, 0.f, 0.f};   // [rt*2 + half]

    // =================== Pass 1: rowsums (MUFU exp2f) ===============
    for (int c = 0; c < NCHUNK; c++) {
        cp_wait<0>();
        __syncthreads();
        if (c + 1 < NCHUNK) prefetch(c + 1);

        const uint32_t boff = (c & 1) * KBUF_STRIDE;
        const char* khS = smem + OFF_KH + boff;
        const char* klS = smem + OFF_KL + boff;

#pragma unroll
        for (int nt = 0; nt < 2; nt++) {
            const int kb = w * 16 + nt * 8 + g;
            uint32_t bH[2][2], bL[2][2];
#pragma unroll
            for (int ks = 0; ks < 2; ks++) {
                const int c0 = ks * 16;
                bH[ks][0] = *reinterpret_cast<const uint32_t*>(khS + kb * 80 + (c0 + 2 * t) * 2);
                bH[ks][1] = *reinterpret_cast<const uint32_t*>(khS + kb * 80 + (c0 + 2 * t + 8) * 2);
                bL[ks][0] = *reinterpret_cast<const uint32_t*>(klS + kb * 80 + (c0 + 2 * t) * 2);
                bL[ks][1] = *reinterpret_cast<const uint32_t*>(klS + kb * 80 + (c0 + 2 * t + 8) * 2);
            }
#pragma unroll
            for (int rt = 0; rt < 4; rt++) {
                float d0 = 0.f, d1 = 0.f, d2 = 0.f, d3 = 0.f;
#pragma unroll
                for (int ks = 0; ks < 2; ks++) {
                    mma_bf16(d0, d1, d2, d3, aH[rt][ks], bH[ks][0], bH[ks][1]);
                    mma_bf16(d0, d1, d2, d3, aL[rt][ks], bH[ks][0], bH[ks][1]);
                    mma_bf16(d0, d1, d2, d3, aH[rt][ks], bL[ks][0], bL[ks][1]);
                }
                ps[rt * 2 + 0] += exp2f(fmaf(d0, EXP_A, -EXP_B))
                                + exp2f(fmaf(d1, EXP_A, -EXP_B));
                ps[rt * 2 + 1] += exp2f(fmaf(d2, EXP_A, -EXP_B))
                                + exp2f(fmaf(d3, EXP_A, -EXP_B));
            }
        }
    }

    // re-issue chunk 0 for pass 2 (buf0 free: all warps synced past last wait)
    prefetch(0);

    // ---- rowsum reduce: quad shuffle + smem atomics ----
#pragma unroll
    for (int i = 0; i < 8; i++) {
        ps[i] += __shfl_xor_sync(0xffffffffu, ps[i], 1);
        ps[i] += __shfl_xor_sync(0xffffffffu, ps[i], 2);
    }
    if (t == 0) {
#pragma unroll
        for (int rt = 0; rt < 4; rt++) {
            atomicAdd(reinterpret_cast<float*>(smem + OFF_RS + (rt * 16 + g) * 4), ps[rt * 2]);
            atomicAdd(reinterpret_cast<float*>(smem + OFF_RS + (rt * 16 + 8 + g) * 4), ps[rt * 2 + 1]);
        }
    }
    __syncthreads();
    if (tid < ROWS) {
        float s = *reinterpret_cast<float*>(smem + OFF_RS + tid * 4);
        *reinterpret_cast<float*>(smem + OFF_INV + tid * 4) = 1.f / s;
    }
    __syncthreads();

    // per-thread folded exponent offsets: c_r = log2(inv_row) - EXP_B
    float cfold[8];
#pragma unroll
    for (int rt = 0; rt < 4; rt++) {
        float i0 = *reinterpret_cast<float*>(smem + OFF_INV + (rt * 16 + g) * 4);
        float i1 = *reinterpret_cast<float*>(smem + OFF_INV + (rt * 16 + 8 + g) * 4);
        cfold[rt * 2 + 0] = log2f(i0) - EXP_B;
        cfold[rt * 2 + 1] = log2f(i1) - EXP_B;
    }

    // =================== Pass 2: recompute + write (MUFU exp2f) ==============
    float* obase = out + ((size_t)bh * SEQN + qBase) * SEQN;
    for (int c = 0; c < NCHUNK; c++) {
        cp_wait<0>();
        __syncthreads();      // K chunk ready; prev sweep done everywhere
        if (c + 1 < NCHUNK) prefetch(c + 1);

        const uint32_t boff = (c & 1) * KBUF_STRIDE;
        const char* khS = smem + OFF_KH + boff;
        const char* klS = smem + OFF_KL + boff;

#pragma unroll
        for (int nt = 0; nt < 2; nt++) {
            const int kb = w * 16 + nt * 8 + g;
            uint32_t bH[2][2], bL[2][2];
#pragma unroll
            for (int ks = 0; ks < 2; ks++) {
                const int c0 = ks * 16;
                bH[ks][0] = *reinterpret_cast<const uint32_t*>(khS + kb * 80 + (c0 + 2 * t) * 2);
                bH[ks][1] = *reinterpret_cast<const uint32_t*>(khS + kb * 80 + (c0 + 2 * t + 8) * 2);
                bL[ks][0] = *reinterpret_cast<const uint32_t*>(klS + kb * 80 + (c0 + 2 * t) * 2);
                bL[ks][1] = *reinterpret_cast<const uint32_t*>(klS + kb * 80 + (c0 + 2 * t + 8) * 2);
            }

            const int col = w * 16 + nt * 8 + 2 * t;   // local col (even)
#pragma unroll
            for (int rt = 0; rt < 4; rt++) {
                float d0 = 0.f, d1 = 0.f, d2 = 0.f, d3 = 0.f;
#pragma unroll
                for (int ks = 0; ks < 2; ks++) {
                    mma_bf16(d0, d1, d2, d3, aH[rt][ks], bH[ks][0], bH[ks][1]);
                    mma_bf16(d0, d1, d2, d3, aL[rt][ks], bH[ks][0], bH[ks][1]);
                    mma_bf16(d0, d1, d2, d3, aH[rt][ks], bL[ks][0], bL[ks][1]);
                }
                float2 v0, v1;
                v0.x = exp2f(fmaf(d0, EXP_A, cfold[rt * 2 + 0]));
                v0.y = exp2f(fmaf(d1, EXP_A, cfold[rt * 2 + 0]));
                v1.x = exp2f(fmaf(d2, EXP_A, cfold[rt * 2 + 1]));
                v1.y = exp2f(fmaf(d3, EXP_A, cfold[rt * 2 + 1]));
                const int r0 = rt * 16 + g, r1 = rt * 16 + 8 + g;
                *reinterpret_cast<float2*>(smem + OFF_STG + r0 * 544 + col * 4) = v0;
                *reinterpret_cast<float2*>(smem + OFF_STG + r1 * 544 + col * 4) = v1;
            }
        }
        __syncthreads();      // stage complete

        // ---- coalesced stage -> out (64 rows x 512 B, STG.128) ----
        float* ocol = obase + (size_t)c * CHUNK;
#pragma unroll
        for (int s = 0; s < 8; s++) {
            const int i = tid + 256 * s;
            const int r = i >> 5, seg = i & 31;
            uint4 v = *reinterpret_cast<const uint4*>(smem + OFF_STG + r * 544 + seg * 16);
            *reinterpret_cast<uint4*>(ocol + (size_t)r * SEQN + seg * 4) = v;
        }
    }
}

// ---------------------------------------------------------------------------
extern "C" void kernel_launch(void* const* d_in, const int* in_sizes, int n_in,
                              void* d_out, int out_size)
{
    const float* x = (const float*)d_in[0];    // [2,4096,256]
    const float* wmat = (const float*)d_in[1]; // [256,512]
    float* out = (float*)d_out;                // [2,8,4096,4096]

    dummy_kernel<<<1, 32>>>();                 // ncu capture-slot shim

    dim3 g1(TWOC / 64, (BATCH * SEQN) / 64);   // (8, 128)
    qkv_gemm_kernel<<<g1, 256>>>(x, wmat);

    prep_kernel<<<(BATCH * SEQN * 16) / 8, 256>>>();

    cudaFuncSetAttribute(attn_softmax_kernel,
                         cudaFuncAttributeMaxDynamicSharedMemorySize, SMEM_BYTES);
    dim3 g2(SEQN / ROWS, BATCH * NH);          // (64, 16)
    attn_softmax_kernel<<<g2, 256, SMEM_BYTES>>>(out);
}